// round 9
// baseline (speedup 1.0000x reference)
#include <cuda_runtime.h>
#include <math.h>
#include <cstdint>

#define NB 4
#define SS 2048
#define TD 768
#define HID 512
#define NH 8
#define HD 64
#define VD 768
#define MM (NB*SS)   // 8192

// Scratch
__device__ float g_Q[NB*NH*SS*HD];   // [bh][s][d] (tf32-rounded, pre-scaled 1/8)
__device__ float g_K[NB*NH*SS*HD];
__device__ float g_V[NB*NH*SS*HD];
__device__ float g_A[MM*HID];        // attended, [b*s][h*d] (tf32-rounded)
__device__ float g_Xr[MM*TD];        // tf32-rounded inputs/weights
__device__ float g_Wqr[TD*HID];
__device__ float g_Wkr[TD*HID];
__device__ float g_Wvr[TD*HID];
__device__ float g_Wor[HID*VD];

// ---------------------------------------------------------------------------
// Helpers (portable PTX, valid on plain sm_103 target)
// ---------------------------------------------------------------------------
__device__ __forceinline__ uint32_t smem_u32(const void* p) {
    uint32_t a;
    asm("{ .reg .u64 t; cvta.to.shared.u64 t, %1; cvt.u32.u64 %0, t; }" : "=r"(a) : "l"(p));
    return a;
}
__device__ __forceinline__ float tf32r(float x) {
    uint32_t u;
    asm("cvt.rna.tf32.f32 %0, %1;" : "=r"(u) : "f"(x));
    return __uint_as_float(u);
}
__device__ __forceinline__ float4 tf32r4(float4 v) {
    v.x = tf32r(v.x); v.y = tf32r(v.y); v.z = tf32r(v.z); v.w = tf32r(v.w);
    return v;
}
__device__ __forceinline__ void cp16(uint32_t dst, const void* src) {
    asm volatile("cp.async.ca.shared.global [%0], [%1], 16;" :: "r"(dst), "l"(src));
}
#define CP_COMMIT() asm volatile("cp.async.commit_group;" ::: "memory")
#define CP_WAIT0()  asm volatile("cp.async.wait_group 0;" ::: "memory")

// ldmatrix.x4 (tf32 trick: 8x4 tf32 tile == 8x8 b16 tile)
__device__ __forceinline__ void ldsm4(uint32_t* r, uint32_t a) {
    asm volatile("ldmatrix.sync.aligned.m8n8.x4.shared.b16 {%0,%1,%2,%3}, [%4];"
        : "=r"(r[0]), "=r"(r[1]), "=r"(r[2]), "=r"(r[3]) : "r"(a));
}
// A-fragment addresses: m16 x k8 tile at (m0,k0) in row-major [m][k], stride floats
__device__ __forceinline__ uint32_t a_addr(uint32_t base, int stride, int m0, int k0, int lane) {
    int sel = lane >> 3, r = lane & 7;
    return base + (((m0 + ((sel & 1) << 3) + r) * stride) + k0 + ((sel >> 1) << 2)) * 4;
}
// B-fragment addresses: two n-octets at (n0, k0) in [n][k] layout -> {b0,b1,b0',b1'}
__device__ __forceinline__ uint32_t b_addr(uint32_t base, int stride, int n0, int k0, int lane) {
    int sel = lane >> 3, r = lane & 7;
    return base + (((n0 + ((sel >> 1) << 3) + r) * stride) + k0 + ((sel & 1) << 2)) * 4;
}

// m16n8k8 tf32 MMA (g=lane>>2, tig=lane&3):
//  A: a0=[g][tig] a1=[g+8][tig] a2=[g][tig+4] a3=[g+8][tig+4]
//  B: b0=[k=tig][n=g] b1=[k=tig+4][n=g]
//  C: c0=[g][2tig] c1=[g][2tig+1] c2=[g+8][2tig] c3=[g+8][2tig+1]
__device__ __forceinline__ void mma8(float* c, const uint32_t* a, const uint32_t* b) {
    asm volatile(
        "mma.sync.aligned.m16n8k8.row.col.f32.tf32.tf32.f32 "
        "{%0,%1,%2,%3}, {%4,%5,%6,%7}, {%8,%9}, {%0,%1,%2,%3};"
        : "+f"(c[0]), "+f"(c[1]), "+f"(c[2]), "+f"(c[3])
        : "r"(a[0]), "r"(a[1]), "r"(a[2]), "r"(a[3]), "r"(b[0]), "r"(b[1]));
}

// ---------------------------------------------------------------------------
// Kernel 0: RNA-round inputs and weights once.
// ---------------------------------------------------------------------------
__global__ __launch_bounds__(256) void round_pre(
    const float* __restrict__ X,
    const float* __restrict__ Wq, const float* __restrict__ Wk,
    const float* __restrict__ Wv, const float* __restrict__ Wo)
{
    const int stride = gridDim.x * blockDim.x;
    const int i0 = blockIdx.x * blockDim.x + threadIdx.x;
    for (int i = i0; i < MM * TD / 4; i += stride)
        ((float4*)g_Xr)[i] = tf32r4(((const float4*)X)[i]);
    for (int i = i0; i < TD * HID / 4; i += stride) {
        ((float4*)g_Wqr)[i] = tf32r4(((const float4*)Wq)[i]);
        ((float4*)g_Wkr)[i] = tf32r4(((const float4*)Wk)[i]);
        ((float4*)g_Wvr)[i] = tf32r4(((const float4*)Wv)[i]);
        ((float4*)g_Wor)[i] = tf32r4(((const float4*)Wo)[i]);
    }
}

// ===========================================================================
// Projection GEMM body. CTA 64(M) x 128(N), BK=32, 128 threads (4 warps),
// warp tile 32x64, __launch_bounds__(128,4) -> 16 warps/SM (latency hiding).
//   A-frags: ldmatrix from X [m][k] (stride 36, conflict-free)
//   B-frags: scalar LDS from W [k][n] (stride 136, banks 8tig+g+8nj, CF)
// smem floats: X[2][64][36] | W[2][32][136]  (53.2 KB -> 4 CTA/SM)
// ===========================================================================
#define PX0 0
#define PX1 2304
#define PW0 4608
#define PW1 8960
#define PROJ_SMEM (13312 * 4)

__device__ __forceinline__ void proj_issue(
    uint32_t sb, int buf, int kt,
    const float* __restrict__ A, int lda,
    const float* __restrict__ W, int ldw,
    int m0, int n0, int t)
{
    uint32_t xd = sb + (buf ? PX1 : PX0) * 4;
#pragma unroll
    for (int it = 0; it < 4; it++) {
        int i = t + it * 128;
        int r = i >> 3, fg = i & 7;
        cp16(xd + (r * 36 + fg * 4) * 4, &A[(size_t)(m0 + r) * lda + kt + fg * 4]);
    }
    uint32_t wd = sb + (buf ? PW1 : PW0) * 4;
#pragma unroll
    for (int it = 0; it < 8; it++) {
        int i = t + it * 128;
        int r = i >> 5, fg = i & 31;
        cp16(wd + (r * 136 + fg * 4) * 4, &W[(size_t)(kt + r) * ldw + n0 + fg * 4]);
    }
}

__device__ __forceinline__ void proj_body(
    float* sm, uint32_t sb,
    const float* __restrict__ A, int lda,
    const float* __restrict__ W, int ldw,
    int kdim, int m0, int n0, float acc[2][8][4])
{
    const int t = threadIdx.x;
    const int w = t >> 5, lane = t & 31, g = lane >> 2, tig = lane & 3;
    const int mw = (w >> 1) * 32, nw = (w & 1) * 64;

#pragma unroll
    for (int mi = 0; mi < 2; mi++)
#pragma unroll
        for (int nj = 0; nj < 8; nj++)
#pragma unroll
            for (int r = 0; r < 4; r++) acc[mi][nj][r] = 0.f;

    const int nc = kdim >> 5;
    proj_issue(sb, 0, 0, A, lda, W, ldw, m0, n0, t);
    CP_COMMIT();

    for (int c = 0; c < nc; c++) {
        CP_WAIT0();
        __syncthreads();
        if (c + 1 < nc) {
            proj_issue(sb, (c + 1) & 1, (c + 1) << 5, A, lda, W, ldw, m0, n0, t);
            CP_COMMIT();
        }
        uint32_t xb = sb + ((c & 1) ? PX1 : PX0) * 4;
        const float* ws = sm + ((c & 1) ? PW1 : PW0);

#pragma unroll
        for (int ks = 0; ks < 4; ks++) {
            uint32_t af[2][4];
            ldsm4(af[0], a_addr(xb, 36, mw, ks * 8, lane));
            ldsm4(af[1], a_addr(xb, 36, mw + 16, ks * 8, lane));
#pragma unroll
            for (int nj = 0; nj < 8; nj++) {
                uint32_t bf[2];
                bf[0] = __float_as_uint(ws[(ks * 8 + tig) * 136 + nw + nj * 8 + g]);
                bf[1] = __float_as_uint(ws[(ks * 8 + tig + 4) * 136 + nw + nj * 8 + g]);
                mma8(acc[0][nj], af[0], bf);
                mma8(acc[1][nj], af[1], bf);
            }
        }
    }
}

// ---------------------------------------------------------------------------
// Kernel 1: fused QKV projection -> [bh][s][d]; Q pre-scaled by 0.125 (exact)
// ---------------------------------------------------------------------------
__global__ __launch_bounds__(128, 4) void qkv_mma(
    const float* __restrict__ bq, const float* __restrict__ bk,
    const float* __restrict__ bv)
{
    extern __shared__ float sm[];
    uint32_t sb = smem_u32(sm);

    const int z = blockIdx.z;
    const float* W    = (z == 0) ? g_Wqr : (z == 1) ? g_Wkr : g_Wvr;
    const float* bias = (z == 0) ? bq : (z == 1) ? bk : bv;
    float* out        = (z == 0) ? g_Q : (z == 1) ? g_K : g_V;

    const int m0 = blockIdx.y * 64;
    const int n0 = blockIdx.x * 128;

    float acc[2][8][4];
    proj_body(sm, sb, g_Xr, TD, W, HID, TD, m0, n0, acc);

    const int t = threadIdx.x;
    const int w = t >> 5, lane = t & 31, g = lane >> 2, tig = lane & 3;
    const int mw = (w >> 1) * 32, nw = (w & 1) * 64;
    const float qs = (z == 0) ? 0.125f : 1.0f;   // exact power-of-2 prescale

#pragma unroll
    for (int mi = 0; mi < 2; mi++) {
        int r = m0 + mw + 16 * mi + g;
        int b_ = r >> 11, s_ = r & 2047;
#pragma unroll
        for (int nj = 0; nj < 8; nj++) {
            int cg = n0 + nw + nj * 8 + 2 * tig;
            int h = cg >> 6, d = cg & 63;
            float* base0 = out + ((((size_t)(b_ * NH + h)) * SS + s_) << 6) + d;
            float* base1 = base0 + (8 << 6);
            float2 bb = *(const float2*)&bias[cg];
            *(float2*)base0 = make_float2(tf32r(acc[mi][nj][0] + bb.x) * qs,
                                          tf32r(acc[mi][nj][1] + bb.y) * qs);
            *(float2*)base1 = make_float2(tf32r(acc[mi][nj][2] + bb.x) * qs,
                                          tf32r(acc[mi][nj][3] + bb.y) * qs);
        }
    }
}

// ---------------------------------------------------------------------------
// Kernel 3: output projection  out = g_A @ Wo + bo (fp32 output)
// ---------------------------------------------------------------------------
__global__ __launch_bounds__(128, 4) void oproj_mma(
    const float* __restrict__ bo, float* __restrict__ out)
{
    extern __shared__ float sm[];
    uint32_t sb = smem_u32(sm);
    const int m0 = blockIdx.y * 64;
    const int n0 = blockIdx.x * 128;

    float acc[2][8][4];
    proj_body(sm, sb, g_A, HID, g_Wor, VD, HID, m0, n0, acc);

    const int t = threadIdx.x;
    const int w = t >> 5, lane = t & 31, g = lane >> 2, tig = lane & 3;
    const int mw = (w >> 1) * 32, nw = (w & 1) * 64;

#pragma unroll
    for (int mi = 0; mi < 2; mi++) {
        int r = m0 + mw + 16 * mi + g;
        float* base0 = out + (size_t)r * VD + n0 + nw;
        float* base1 = base0 + (size_t)8 * VD;
#pragma unroll
        for (int nj = 0; nj < 8; nj++) {
            int col = nj * 8 + 2 * tig;
            float2 bb = *(const float2*)&bo[n0 + nw + col];
            *(float2*)&base0[col] = make_float2(acc[mi][nj][0] + bb.x, acc[mi][nj][1] + bb.y);
            *(float2*)&base1[col] = make_float2(acc[mi][nj][2] + bb.x, acc[mi][nj][3] + bb.y);
        }
    }
}

// ===========================================================================
// Kernel 2: flash attention. 128 threads (4 warps), q-tile 128 (32 rows/warp),
// key tile 64. Q-fragments persist in registers; Q pre-scaled by 1/8 so the
// softmax consumes S directly (no per-element scale).
// smem floats: K[2][64][68] | V[2][64][72] | P[128][68]
// ===========================================================================
#define AK0 0
#define AK1 4352
#define AV0 8704
#define AV1 13312
#define AP  17920
#define ATTN_SMEM (26624 * 4)
#define NIT (SS / 64)   // 32 key tiles

__device__ __forceinline__ void attn_issue(
    uint32_t sb, int buf, const float* __restrict__ Kg,
    const float* __restrict__ Vg, int kt, int t)
{
    uint32_t kd = sb + (buf ? AK1 : AK0) * 4;
    uint32_t vd = sb + (buf ? AV1 : AV0) * 4;
    const float* Kt = Kg + (size_t)kt * 64 * 64;
    const float* Vt = Vg + (size_t)kt * 64 * 64;
#pragma unroll
    for (int it = 0; it < 8; it++) {
        int i = t + it * 128;
        int r = i >> 4, fg = i & 15;
        cp16(kd + (r * 68 + fg * 4) * 4, &Kt[r * 64 + fg * 4]);
        cp16(vd + (r * 72 + fg * 4) * 4, &Vt[r * 64 + fg * 4]);
    }
}

__global__ __launch_bounds__(128, 1) void attn_mma()
{
    extern __shared__ float sm[];
    uint32_t sb = smem_u32(sm);
    const int t = threadIdx.x;
    const int w = t >> 5, lane = t & 31, g = lane >> 2, tig = lane & 3;
    const int qt = blockIdx.x, bh = blockIdx.y;
    const int mrow = w * 32;

    const float* Qg = g_Q + (size_t)bh * SS * HD;
    const float* Kg = g_K + (size_t)bh * SS * HD;
    const float* Vg = g_V + (size_t)bh * SS * HD;

    // Stage Q [128][68] (pre-scaled) into the K region, extract frags, free.
#pragma unroll
    for (int it = 0; it < 16; it++) {
        int i = t + it * 128;
        int r = i >> 4, fg = i & 15;
        *(float4*)&sm[r * 68 + fg * 4] =
            *(const float4*)&Qg[(size_t)(qt * 128 + r) * 64 + fg * 4];
    }
    __syncthreads();
    uint32_t qa[8][2][4];
#pragma unroll
    for (int ks = 0; ks < 8; ks++) {
        ldsm4(qa[ks][0], a_addr(sb, 68, mrow, ks * 8, lane));
        ldsm4(qa[ks][1], a_addr(sb, 68, mrow + 16, ks * 8, lane));
    }
    __syncthreads();   // Q reads done; K/V region may be overwritten

    attn_issue(sb, 0, Kg, Vg, 0, t);
    CP_COMMIT();

    float o[2][8][4];
#pragma unroll
    for (int mt = 0; mt < 2; mt++)
#pragma unroll
        for (int nj = 0; nj < 8; nj++)
#pragma unroll
            for (int r = 0; r < 4; r++) o[mt][nj][r] = 0.f;
    float mr[2][2] = {{-1e30f, -1e30f}, {-1e30f, -1e30f}};
    float lr[2][2] = {{0.f, 0.f}, {0.f, 0.f}};

    for (int kt = 0; kt < NIT; kt++) {
        CP_WAIT0();
        __syncthreads();
        if (kt + 1 < NIT) {
            attn_issue(sb, (kt + 1) & 1, Kg, Vg, kt + 1, t);
            CP_COMMIT();
        }
        uint32_t kb = sb + ((kt & 1) ? AK1 : AK0) * 4;

        // S = Q K^T (pre-scaled), 32 rows x 64 keys per warp
        float s[2][8][4];
#pragma unroll
        for (int mt = 0; mt < 2; mt++)
#pragma unroll
            for (int nj = 0; nj < 8; nj++)
#pragma unroll
                for (int r = 0; r < 4; r++) s[mt][nj][r] = 0.f;

#pragma unroll
        for (int ks = 0; ks < 8; ks++)
#pragma unroll
            for (int p = 0; p < 4; p++) {
                uint32_t bf[4];
                ldsm4(bf, b_addr(kb, 68, p * 16, ks * 8, lane));
                mma8(s[0][p * 2],     qa[ks][0], bf);
                mma8(s[0][p * 2 + 1], qa[ks][0], bf + 2);
                mma8(s[1][p * 2],     qa[ks][1], bf);
                mma8(s[1][p * 2 + 1], qa[ks][1], bf + 2);
            }

        // Online softmax (S already scaled)
        float corr[2][2];
#pragma unroll
        for (int mt = 0; mt < 2; mt++) {
            float mx0 = mr[mt][0], mx1 = mr[mt][1];
#pragma unroll
            for (int nj = 0; nj < 8; nj++) {
                mx0 = fmaxf(mx0, fmaxf(s[mt][nj][0], s[mt][nj][1]));
                mx1 = fmaxf(mx1, fmaxf(s[mt][nj][2], s[mt][nj][3]));
            }
            mx0 = fmaxf(mx0, __shfl_xor_sync(0xffffffffu, mx0, 1));
            mx0 = fmaxf(mx0, __shfl_xor_sync(0xffffffffu, mx0, 2));
            mx1 = fmaxf(mx1, __shfl_xor_sync(0xffffffffu, mx1, 1));
            mx1 = fmaxf(mx1, __shfl_xor_sync(0xffffffffu, mx1, 2));

            corr[mt][0] = __expf(mr[mt][0] - mx0);
            corr[mt][1] = __expf(mr[mt][1] - mx1);
            float ls0 = 0.f, ls1 = 0.f;
            int row0 = mrow + 16 * mt + g;
#pragma unroll
            for (int nj = 0; nj < 8; nj++) {
                float p0 = __expf(s[mt][nj][0] - mx0);
                float p1 = __expf(s[mt][nj][1] - mx0);
                float p2 = __expf(s[mt][nj][2] - mx1);
                float p3 = __expf(s[mt][nj][3] - mx1);
                ls0 += p0 + p1;
                ls1 += p2 + p3;
                *(float2*)&sm[AP + row0 * 68 + nj * 8 + 2 * tig] =
                    make_float2(tf32r(p0), tf32r(p1));
                *(float2*)&sm[AP + (row0 + 8) * 68 + nj * 8 + 2 * tig] =
                    make_float2(tf32r(p2), tf32r(p3));
            }
            ls0 += __shfl_xor_sync(0xffffffffu, ls0, 1);
            ls0 += __shfl_xor_sync(0xffffffffu, ls0, 2);
            ls1 += __shfl_xor_sync(0xffffffffu, ls1, 1);
            ls1 += __shfl_xor_sync(0xffffffffu, ls1, 2);
            lr[mt][0] = lr[mt][0] * corr[mt][0] + ls0;
            lr[mt][1] = lr[mt][1] * corr[mt][1] + ls1;
            mr[mt][0] = mx0; mr[mt][1] = mx1;

#pragma unroll
            for (int nj = 0; nj < 8; nj++) {
                o[mt][nj][0] *= corr[mt][0]; o[mt][nj][1] *= corr[mt][0];
                o[mt][nj][2] *= corr[mt][1]; o[mt][nj][3] *= corr[mt][1];
            }
        }
        __syncwarp();   // P rows are warp-private

        // O += P V   (keys = 8 k-steps of 8; V [k][n] scalar B-frags)
        uint32_t pb = sb + AP * 4;
        const float* vs = sm + ((kt & 1) ? AV1 : AV0);
#pragma unroll
        for (int ks = 0; ks < 8; ks++) {
            uint32_t pa0[4], pa1[4];
            ldsm4(pa0, a_addr(pb, 68, mrow, ks * 8, lane));
            ldsm4(pa1, a_addr(pb, 68, mrow + 16, ks * 8, lane));
#pragma unroll
            for (int nj = 0; nj < 8; nj++) {
                uint32_t bf[2];
                bf[0] = __float_as_uint(vs[(ks * 8 + tig) * 72 + nj * 8 + g]);
                bf[1] = __float_as_uint(vs[(ks * 8 + tig + 4) * 72 + nj * 8 + g]);
                mma8(o[0][nj], pa0, bf);
                mma8(o[1][nj], pa1, bf);
            }
        }
    }

    // Epilogue: normalize, round, write g_A [b*s][h*64]
    const int b_ = bh >> 3, h = bh & 7;
#pragma unroll
    for (int mt = 0; mt < 2; mt++) {
        float inv0 = 1.f / lr[mt][0], inv1 = 1.f / lr[mt][1];
        int r0 = qt * 128 + mrow + 16 * mt + g;
        float* p0 = g_A + ((size_t)(b_ * SS + r0)) * HID + h * 64;
        float* p1 = p0 + (size_t)8 * HID;
#pragma unroll
        for (int nj = 0; nj < 8; nj++) {
            *(float2*)&p0[nj * 8 + 2 * tig] =
                make_float2(tf32r(o[mt][nj][0] * inv0), tf32r(o[mt][nj][1] * inv0));
            *(float2*)&p1[nj * 8 + 2 * tig] =
                make_float2(tf32r(o[mt][nj][2] * inv1), tf32r(o[mt][nj][3] * inv1));
        }
    }
}

// ===========================================================================
extern "C" void kernel_launch(void* const* d_in, const int* in_sizes, int n_in,
                              void* d_out, int out_size)
{
    const float* X  = (const float*)d_in[0];
    const float* Wq = (const float*)d_in[1];
    const float* bq = (const float*)d_in[2];
    const float* Wk = (const float*)d_in[3];
    const float* bk = (const float*)d_in[4];
    const float* Wv = (const float*)d_in[5];
    const float* bv = (const float*)d_in[6];
    const float* Wo = (const float*)d_in[7];
    const float* bo = (const float*)d_in[8];
    float* out = (float*)d_out;

    cudaFuncSetAttribute(qkv_mma,   cudaFuncAttributeMaxDynamicSharedMemorySize, PROJ_SMEM);
    cudaFuncSetAttribute(oproj_mma, cudaFuncAttributeMaxDynamicSharedMemorySize, PROJ_SMEM);
    cudaFuncSetAttribute(attn_mma,  cudaFuncAttributeMaxDynamicSharedMemorySize, ATTN_SMEM);

    round_pre<<<1184, 256>>>(X, Wq, Wk, Wv, Wo);
    qkv_mma<<<dim3(HID / 128, MM / 64, 3), 128, PROJ_SMEM>>>(bq, bk, bv);
    attn_mma<<<dim3(SS / 128, NB * NH), 128, ATTN_SMEM>>>();
    oproj_mma<<<dim3(VD / 128, MM / 64), 128, PROJ_SMEM>>>(bo, out);
}

// round 10
// speedup vs baseline: 1.0396x; 1.0396x over previous
#include <cuda_runtime.h>
#include <math.h>
#include <cstdint>

#define NB 4
#define SS 2048
#define TD 768
#define HID 512
#define NH 8
#define HD 64
#define VD 768
#define MM (NB*SS)   // 8192

// Scratch
__device__ float g_Q[NB*NH*SS*HD];   // [bh][s][d] (tf32-rounded, pre-scaled 1/8)
__device__ float g_K[NB*NH*SS*HD];   // [bh][s][d]
__device__ float g_V[NB*NH*SS*HD];   // [bh][s][d]
__device__ float g_Vt[NB*NH*SS*HD];  // [bh][d][s]  (transposed V)
__device__ float g_A[MM*HID];        // attended, [b*s][h*d] (tf32-rounded)
__device__ float g_Xr[MM*TD];        // tf32-rounded X
__device__ float g_Wqt[HID*TD];      // tf32-rounded, TRANSPOSED weights [n][k]
__device__ float g_Wkt[HID*TD];
__device__ float g_Wvt[HID*TD];
__device__ float g_Wot[VD*HID];

// ---------------------------------------------------------------------------
// Helpers (portable PTX, valid on plain sm_103 target)
// ---------------------------------------------------------------------------
__device__ __forceinline__ uint32_t smem_u32(const void* p) {
    uint32_t a;
    asm("{ .reg .u64 t; cvta.to.shared.u64 t, %1; cvt.u32.u64 %0, t; }" : "=r"(a) : "l"(p));
    return a;
}
__device__ __forceinline__ float tf32r(float x) {
    uint32_t u;
    asm("cvt.rna.tf32.f32 %0, %1;" : "=r"(u) : "f"(x));
    return __uint_as_float(u);
}
__device__ __forceinline__ float4 tf32r4(float4 v) {
    v.x = tf32r(v.x); v.y = tf32r(v.y); v.z = tf32r(v.z); v.w = tf32r(v.w);
    return v;
}
__device__ __forceinline__ void cp16(uint32_t dst, const void* src) {
    asm volatile("cp.async.ca.shared.global [%0], [%1], 16;" :: "r"(dst), "l"(src));
}
#define CP_COMMIT() asm volatile("cp.async.commit_group;" ::: "memory")
#define CP_WAIT0()  asm volatile("cp.async.wait_group 0;" ::: "memory")

// ldmatrix.x4 (tf32 trick: 8x4 tf32 tile == 8x8 b16 tile)
__device__ __forceinline__ void ldsm4(uint32_t* r, uint32_t a) {
    asm volatile("ldmatrix.sync.aligned.m8n8.x4.shared.b16 {%0,%1,%2,%3}, [%4];"
        : "=r"(r[0]), "=r"(r[1]), "=r"(r[2]), "=r"(r[3]) : "r"(a));
}
// A-fragment addresses: m16 x k8 tile at (m0,k0) in row-major [m][k], stride floats
__device__ __forceinline__ uint32_t a_addr(uint32_t base, int stride, int m0, int k0, int lane) {
    int sel = lane >> 3, r = lane & 7;
    return base + (((m0 + ((sel & 1) << 3) + r) * stride) + k0 + ((sel >> 1) << 2)) * 4;
}
// B-fragment addresses: two n-octets at (n0, k0) in [n][k] layout -> {b0,b1,b0',b1'}
__device__ __forceinline__ uint32_t b_addr(uint32_t base, int stride, int n0, int k0, int lane) {
    int sel = lane >> 3, r = lane & 7;
    return base + (((n0 + ((sel >> 1) << 3) + r) * stride) + k0 + ((sel & 1) << 2)) * 4;
}

// m16n8k8 tf32 MMA (g=lane>>2, tig=lane&3):
//  A: a0=[g][tig] a1=[g+8][tig] a2=[g][tig+4] a3=[g+8][tig+4]
//  B: b0=[k=tig][n=g] b1=[k=tig+4][n=g]
//  C: c0=[g][2tig] c1=[g][2tig+1] c2=[g+8][2tig] c3=[g+8][2tig+1]
__device__ __forceinline__ void mma8(float* c, const uint32_t* a, const uint32_t* b) {
    asm volatile(
        "mma.sync.aligned.m16n8k8.row.col.f32.tf32.tf32.f32 "
        "{%0,%1,%2,%3}, {%4,%5,%6,%7}, {%8,%9}, {%0,%1,%2,%3};"
        : "+f"(c[0]), "+f"(c[1]), "+f"(c[2]), "+f"(c[3])
        : "r"(a[0]), "r"(a[1]), "r"(a[2]), "r"(a[3]), "r"(b[0]), "r"(b[1]));
}

// ---------------------------------------------------------------------------
// Kernel 0a: RNA-round X
// ---------------------------------------------------------------------------
__global__ __launch_bounds__(256) void round_x(const float* __restrict__ X)
{
    const int stride = gridDim.x * blockDim.x;
    for (int i = blockIdx.x * blockDim.x + threadIdx.x; i < MM * TD / 4; i += stride)
        ((float4*)g_Xr)[i] = tf32r4(((const float4*)X)[i]);
}

// ---------------------------------------------------------------------------
// Kernel 0b: RNA-round + TRANSPOSE weights [k][n] -> [n][k]
// ---------------------------------------------------------------------------
__global__ __launch_bounds__(256) void round_wt(
    const float* __restrict__ Wq, const float* __restrict__ Wk,
    const float* __restrict__ Wv, const float* __restrict__ Wo)
{
    __shared__ float tile[32][33];
    const int z = blockIdx.z;
    const float* W; float* Wt; int K, N;
    if (z < 3) { K = TD; N = HID; W = (z == 0) ? Wq : (z == 1) ? Wk : Wv;
                 Wt = (z == 0) ? g_Wqt : (z == 1) ? g_Wkt : g_Wvt; }
    else       { K = HID; N = VD; W = Wo; Wt = g_Wot; }

    const int n0 = blockIdx.x * 32, k0 = blockIdx.y * 32;
    if (n0 >= N || k0 >= K) return;
    const int tx = threadIdx.x & 31, ty = threadIdx.x >> 5;   // 32 x 8
#pragma unroll
    for (int i = 0; i < 4; i++)
        tile[ty + 8 * i][tx] = tf32r(W[(size_t)(k0 + ty + 8 * i) * N + n0 + tx]);
    __syncthreads();
#pragma unroll
    for (int i = 0; i < 4; i++)
        Wt[(size_t)(n0 + ty + 8 * i) * K + k0 + tx] = tile[tx][ty + 8 * i];
}

// ---------------------------------------------------------------------------
// Kernel 1.5: transpose V [bh][s][d] -> g_Vt [bh][d][s]
// ---------------------------------------------------------------------------
__global__ __launch_bounds__(256) void vt_kernel()
{
    __shared__ float tile[32][33];
    const int bh = blockIdx.z;
    const int d0 = blockIdx.x * 32, s0 = blockIdx.y * 32;
    const float* V = g_V + (size_t)bh * SS * HD;
    float* Vt = g_Vt + (size_t)bh * SS * HD;
    const int tx = threadIdx.x & 31, ty = threadIdx.x >> 5;
#pragma unroll
    for (int i = 0; i < 4; i++)
        tile[ty + 8 * i][tx] = V[(size_t)(s0 + ty + 8 * i) * HD + d0 + tx];
    __syncthreads();
#pragma unroll
    for (int i = 0; i < 4; i++)
        Vt[(size_t)(d0 + ty + 8 * i) * SS + s0 + tx] = tile[tx][ty + 8 * i];
}

// ===========================================================================
// Projection GEMM body. CTA 128(M) x 128(N), BK=32, 128 threads (4 warps),
// warp tile 64x64. Weights pre-transposed [n][k] -> BOTH operands via
// ldmatrix.x4 (8 load-instr per ks for 32 MMAs; 1.0 wf/MMA).
// smem floats: X[2][128][36] | Wt[2][128][36]   (73.7 KB -> 2 CTA/SM)
// ===========================================================================
#define PX0 0
#define PX1 4608
#define PW0 9216
#define PW1 13824
#define PROJ_SMEM (18432 * 4)

__device__ __forceinline__ void proj_issue(
    uint32_t sb, int buf, int kt,
    const float* __restrict__ A, int lda,
    const float* __restrict__ Wt, int ldw,
    int m0, int n0, int t)
{
    uint32_t xd = sb + (buf ? PX1 : PX0) * 4;
#pragma unroll
    for (int it = 0; it < 8; it++) {
        int i = t + it * 128;
        int r = i >> 3, fg = i & 7;
        cp16(xd + (r * 36 + fg * 4) * 4, &A[(size_t)(m0 + r) * lda + kt + fg * 4]);
    }
    uint32_t wd = sb + (buf ? PW1 : PW0) * 4;
#pragma unroll
    for (int it = 0; it < 8; it++) {
        int i = t + it * 128;
        int r = i >> 3, fg = i & 7;
        cp16(wd + (r * 36 + fg * 4) * 4, &Wt[(size_t)(n0 + r) * ldw + kt + fg * 4]);
    }
}

__device__ __forceinline__ void proj_body(
    uint32_t sb,
    const float* __restrict__ A, int lda,
    const float* __restrict__ Wt, int ldw,
    int kdim, int m0, int n0, float acc[4][8][4])
{
    const int t = threadIdx.x;
    const int w = t >> 5, lane = t & 31;
    const int mw = (w >> 1) * 64, nw = (w & 1) * 64;

#pragma unroll
    for (int mi = 0; mi < 4; mi++)
#pragma unroll
        for (int nj = 0; nj < 8; nj++)
#pragma unroll
            for (int r = 0; r < 4; r++) acc[mi][nj][r] = 0.f;

    const int nc = kdim >> 5;
    proj_issue(sb, 0, 0, A, lda, Wt, ldw, m0, n0, t);
    CP_COMMIT();

    for (int c = 0; c < nc; c++) {
        CP_WAIT0();
        __syncthreads();
        if (c + 1 < nc) {
            proj_issue(sb, (c + 1) & 1, (c + 1) << 5, A, lda, Wt, ldw, m0, n0, t);
            CP_COMMIT();
        }
        uint32_t xb = sb + ((c & 1) ? PX1 : PX0) * 4;
        uint32_t wb = sb + ((c & 1) ? PW1 : PW0) * 4;

#pragma unroll
        for (int ks = 0; ks < 4; ks++) {
            uint32_t af[4][4], bf[4][4];
#pragma unroll
            for (int mi = 0; mi < 4; mi++)
                ldsm4(af[mi], a_addr(xb, 36, mw + 16 * mi, ks * 8, lane));
#pragma unroll
            for (int p = 0; p < 4; p++)
                ldsm4(bf[p], b_addr(wb, 36, nw + p * 16, ks * 8, lane));
#pragma unroll
            for (int mi = 0; mi < 4; mi++)
#pragma unroll
                for (int p = 0; p < 4; p++) {
                    mma8(acc[mi][p * 2],     af[mi], bf[p]);
                    mma8(acc[mi][p * 2 + 1], af[mi], bf[p] + 2);
                }
        }
    }
}

// ---------------------------------------------------------------------------
// Kernel 1: fused QKV projection -> [bh][s][d]; Q pre-scaled by 0.125 (exact)
// ---------------------------------------------------------------------------
__global__ __launch_bounds__(128) void qkv_mma(
    const float* __restrict__ bq, const float* __restrict__ bk,
    const float* __restrict__ bv)
{
    extern __shared__ float sm[];
    uint32_t sb = smem_u32(sm);

    const int z = blockIdx.z;
    const float* Wt   = (z == 0) ? g_Wqt : (z == 1) ? g_Wkt : g_Wvt;
    const float* bias = (z == 0) ? bq : (z == 1) ? bk : bv;
    float* out        = (z == 0) ? g_Q : (z == 1) ? g_K : g_V;

    const int m0 = blockIdx.y * 128;
    const int n0 = blockIdx.x * 128;

    float acc[4][8][4];
    proj_body(sb, g_Xr, TD, Wt, TD, TD, m0, n0, acc);

    const int t = threadIdx.x;
    const int w = t >> 5, lane = t & 31, g = lane >> 2, tig = lane & 3;
    const int mw = (w >> 1) * 64, nw = (w & 1) * 64;
    const float qs = (z == 0) ? 0.125f : 1.0f;   // exact power-of-2 prescale

#pragma unroll
    for (int mi = 0; mi < 4; mi++) {
        int r = m0 + mw + 16 * mi + g;
        int b_ = r >> 11, s_ = r & 2047;
#pragma unroll
        for (int nj = 0; nj < 8; nj++) {
            int cg = n0 + nw + nj * 8 + 2 * tig;
            int h = cg >> 6, d = cg & 63;
            float* base0 = out + ((((size_t)(b_ * NH + h)) * SS + s_) << 6) + d;
            float* base1 = base0 + (8 << 6);
            float2 bb = *(const float2*)&bias[cg];
            *(float2*)base0 = make_float2(tf32r(acc[mi][nj][0] + bb.x) * qs,
                                          tf32r(acc[mi][nj][1] + bb.y) * qs);
            *(float2*)base1 = make_float2(tf32r(acc[mi][nj][2] + bb.x) * qs,
                                          tf32r(acc[mi][nj][3] + bb.y) * qs);
        }
    }
}

// ---------------------------------------------------------------------------
// Kernel 3: output projection  out = g_A @ Wo + bo (fp32 output)
// ---------------------------------------------------------------------------
__global__ __launch_bounds__(128) void oproj_mma(
    const float* __restrict__ bo, float* __restrict__ out)
{
    extern __shared__ float sm[];
    uint32_t sb = smem_u32(sm);
    const int m0 = blockIdx.y * 128;
    const int n0 = blockIdx.x * 128;

    float acc[4][8][4];
    proj_body(sb, g_A, HID, g_Wot, HID, HID, m0, n0, acc);

    const int t = threadIdx.x;
    const int w = t >> 5, lane = t & 31, g = lane >> 2, tig = lane & 3;
    const int mw = (w >> 1) * 64, nw = (w & 1) * 64;

#pragma unroll
    for (int mi = 0; mi < 4; mi++) {
        int r = m0 + mw + 16 * mi + g;
        float* base0 = out + (size_t)r * VD + n0 + nw;
        float* base1 = base0 + (size_t)8 * VD;
#pragma unroll
        for (int nj = 0; nj < 8; nj++) {
            int col = nj * 8 + 2 * tig;
            float2 bb = *(const float2*)&bo[n0 + nw + col];
            *(float2*)&base0[col] = make_float2(acc[mi][nj][0] + bb.x, acc[mi][nj][1] + bb.y);
            *(float2*)&base1[col] = make_float2(acc[mi][nj][2] + bb.x, acc[mi][nj][3] + bb.y);
        }
    }
}

// ===========================================================================
// Kernel 2: flash attention. 128 threads (4 warps), q-tile 128 (32 rows/warp),
// key tile 64. Q-fragments persist in registers (Q pre-scaled 1/8).
// K [s][d] and Vt [d][s] both consumed via ldmatrix B-fragments.
// smem floats: K[2][64][68] | Vt[2][64][68] | P[128][68]
// ===========================================================================
#define AK0 0
#define AK1 4352
#define AV0 8704
#define AV1 13056
#define AP  17408
#define ATTN_SMEM (26112 * 4)
#define NIT (SS / 64)   // 32 key tiles

__device__ __forceinline__ void attn_issue(
    uint32_t sb, int buf, const float* __restrict__ Kg,
    const float* __restrict__ Vtg, int kt, int t)
{
    uint32_t kd = sb + (buf ? AK1 : AK0) * 4;
    uint32_t vd = sb + (buf ? AV1 : AV0) * 4;
    const float* Kt = Kg + (size_t)kt * 64 * 64;
#pragma unroll
    for (int it = 0; it < 8; it++) {
        int i = t + it * 128;
        int r = i >> 4, fg = i & 15;
        cp16(kd + (r * 68 + fg * 4) * 4, &Kt[r * 64 + fg * 4]);
        // Vt rows are d (stride SS), columns are s within this key tile
        cp16(vd + (r * 68 + fg * 4) * 4, &Vtg[(size_t)r * SS + kt * 64 + fg * 4]);
    }
}

__global__ __launch_bounds__(128) void attn_mma()
{
    extern __shared__ float sm[];
    uint32_t sb = smem_u32(sm);
    const int t = threadIdx.x;
    const int w = t >> 5, lane = t & 31, g = lane >> 2, tig = lane & 3;
    const int qt = blockIdx.x, bh = blockIdx.y;
    const int mrow = w * 32;

    const float* Qg  = g_Q  + (size_t)bh * SS * HD;
    const float* Kg  = g_K  + (size_t)bh * SS * HD;
    const float* Vtg = g_Vt + (size_t)bh * SS * HD;

    // Stage Q [128][68] (pre-scaled) into the K region, extract frags, free.
#pragma unroll
    for (int it = 0; it < 16; it++) {
        int i = t + it * 128;
        int r = i >> 4, fg = i & 15;
        *(float4*)&sm[r * 68 + fg * 4] =
            *(const float4*)&Qg[(size_t)(qt * 128 + r) * 64 + fg * 4];
    }
    __syncthreads();
    uint32_t qa[8][2][4];
#pragma unroll
    for (int ks = 0; ks < 8; ks++) {
        ldsm4(qa[ks][0], a_addr(sb, 68, mrow, ks * 8, lane));
        ldsm4(qa[ks][1], a_addr(sb, 68, mrow + 16, ks * 8, lane));
    }
    __syncthreads();   // Q reads done; K/V region may be overwritten

    attn_issue(sb, 0, Kg, Vtg, 0, t);
    CP_COMMIT();

    float o[2][8][4];
#pragma unroll
    for (int mt = 0; mt < 2; mt++)
#pragma unroll
        for (int nj = 0; nj < 8; nj++)
#pragma unroll
            for (int r = 0; r < 4; r++) o[mt][nj][r] = 0.f;
    float mr[2][2] = {{-1e30f, -1e30f}, {-1e30f, -1e30f}};
    float lr[2][2] = {{0.f, 0.f}, {0.f, 0.f}};

    for (int kt = 0; kt < NIT; kt++) {
        CP_WAIT0();
        __syncthreads();
        if (kt + 1 < NIT) {
            attn_issue(sb, (kt + 1) & 1, Kg, Vtg, kt + 1, t);
            CP_COMMIT();
        }
        uint32_t kb = sb + ((kt & 1) ? AK1 : AK0) * 4;

        // S = Q K^T (pre-scaled), 32 rows x 64 keys per warp
        float s[2][8][4];
#pragma unroll
        for (int mt = 0; mt < 2; mt++)
#pragma unroll
            for (int nj = 0; nj < 8; nj++)
#pragma unroll
                for (int r = 0; r < 4; r++) s[mt][nj][r] = 0.f;

#pragma unroll
        for (int ks = 0; ks < 8; ks++)
#pragma unroll
            for (int p = 0; p < 4; p++) {
                uint32_t bf[4];
                ldsm4(bf, b_addr(kb, 68, p * 16, ks * 8, lane));
                mma8(s[0][p * 2],     qa[ks][0], bf);
                mma8(s[0][p * 2 + 1], qa[ks][0], bf + 2);
                mma8(s[1][p * 2],     qa[ks][1], bf);
                mma8(s[1][p * 2 + 1], qa[ks][1], bf + 2);
            }

        // Online softmax (S already scaled)
        float corr[2][2];
#pragma unroll
        for (int mt = 0; mt < 2; mt++) {
            float mx0 = mr[mt][0], mx1 = mr[mt][1];
#pragma unroll
            for (int nj = 0; nj < 8; nj++) {
                mx0 = fmaxf(mx0, fmaxf(s[mt][nj][0], s[mt][nj][1]));
                mx1 = fmaxf(mx1, fmaxf(s[mt][nj][2], s[mt][nj][3]));
            }
            mx0 = fmaxf(mx0, __shfl_xor_sync(0xffffffffu, mx0, 1));
            mx0 = fmaxf(mx0, __shfl_xor_sync(0xffffffffu, mx0, 2));
            mx1 = fmaxf(mx1, __shfl_xor_sync(0xffffffffu, mx1, 1));
            mx1 = fmaxf(mx1, __shfl_xor_sync(0xffffffffu, mx1, 2));

            corr[mt][0] = __expf(mr[mt][0] - mx0);
            corr[mt][1] = __expf(mr[mt][1] - mx1);
            float ls0 = 0.f, ls1 = 0.f;
            int row0 = mrow + 16 * mt + g;
#pragma unroll
            for (int nj = 0; nj < 8; nj++) {
                float p0 = __expf(s[mt][nj][0] - mx0);
                float p1 = __expf(s[mt][nj][1] - mx0);
                float p2 = __expf(s[mt][nj][2] - mx1);
                float p3 = __expf(s[mt][nj][3] - mx1);
                ls0 += p0 + p1;
                ls1 += p2 + p3;
                *(float2*)&sm[AP + row0 * 68 + nj * 8 + 2 * tig] =
                    make_float2(tf32r(p0), tf32r(p1));
                *(float2*)&sm[AP + (row0 + 8) * 68 + nj * 8 + 2 * tig] =
                    make_float2(tf32r(p2), tf32r(p3));
            }
            ls0 += __shfl_xor_sync(0xffffffffu, ls0, 1);
            ls0 += __shfl_xor_sync(0xffffffffu, ls0, 2);
            ls1 += __shfl_xor_sync(0xffffffffu, ls1, 1);
            ls1 += __shfl_xor_sync(0xffffffffu, ls1, 2);
            lr[mt][0] = lr[mt][0] * corr[mt][0] + ls0;
            lr[mt][1] = lr[mt][1] * corr[mt][1] + ls1;
            mr[mt][0] = mx0; mr[mt][1] = mx1;

#pragma unroll
            for (int nj = 0; nj < 8; nj++) {
                o[mt][nj][0] *= corr[mt][0]; o[mt][nj][1] *= corr[mt][0];
                o[mt][nj][2] *= corr[mt][1]; o[mt][nj][3] *= corr[mt][1];
            }
        }
        __syncwarp();   // P rows are warp-private

        // O += P V   (A: P-frags via ldsm; B: Vt [d][s] via ldsm)
        uint32_t pb = sb + AP * 4;
        uint32_t vb = sb + ((kt & 1) ? AV1 : AV0) * 4;
#pragma unroll
        for (int ks = 0; ks < 8; ks++) {
            uint32_t pa0[4], pa1[4];
            ldsm4(pa0, a_addr(pb, 68, mrow, ks * 8, lane));
            ldsm4(pa1, a_addr(pb, 68, mrow + 16, ks * 8, lane));
#pragma unroll
            for (int p = 0; p < 4; p++) {
                uint32_t bf[4];
                ldsm4(bf, b_addr(vb, 68, p * 16, ks * 8, lane));
                mma8(o[0][p * 2],     pa0, bf);
                mma8(o[0][p * 2 + 1], pa0, bf + 2);
                mma8(o[1][p * 2],     pa1, bf);
                mma8(o[1][p * 2 + 1], pa1, bf + 2);
            }
        }
    }

    // Epilogue: normalize, round, write g_A [b*s][h*64]
    const int b_ = bh >> 3, h = bh & 7;
#pragma unroll
    for (int mt = 0; mt < 2; mt++) {
        float inv0 = 1.f / lr[mt][0], inv1 = 1.f / lr[mt][1];
        int r0 = qt * 128 + mrow + 16 * mt + g;
        float* p0 = g_A + ((size_t)(b_ * SS + r0)) * HID + h * 64;
        float* p1 = p0 + (size_t)8 * HID;
#pragma unroll
        for (int nj = 0; nj < 8; nj++) {
            *(float2*)&p0[nj * 8 + 2 * tig] =
                make_float2(tf32r(o[mt][nj][0] * inv0), tf32r(o[mt][nj][1] * inv0));
            *(float2*)&p1[nj * 8 + 2 * tig] =
                make_float2(tf32r(o[mt][nj][2] * inv1), tf32r(o[mt][nj][3] * inv1));
        }
    }
}

// ===========================================================================
extern "C" void kernel_launch(void* const* d_in, const int* in_sizes, int n_in,
                              void* d_out, int out_size)
{
    const float* X  = (const float*)d_in[0];
    const float* Wq = (const float*)d_in[1];
    const float* bq = (const float*)d_in[2];
    const float* Wk = (const float*)d_in[3];
    const float* bk = (const float*)d_in[4];
    const float* Wv = (const float*)d_in[5];
    const float* bv = (const float*)d_in[6];
    const float* Wo = (const float*)d_in[7];
    const float* bo = (const float*)d_in[8];
    float* out = (float*)d_out;

    cudaFuncSetAttribute(qkv_mma,   cudaFuncAttributeMaxDynamicSharedMemorySize, PROJ_SMEM);
    cudaFuncSetAttribute(oproj_mma, cudaFuncAttributeMaxDynamicSharedMemorySize, PROJ_SMEM);
    cudaFuncSetAttribute(attn_mma,  cudaFuncAttributeMaxDynamicSharedMemorySize, ATTN_SMEM);

    round_x<<<592, 256>>>(X);
    round_wt<<<dim3(24, 24, 4), 256>>>(Wq, Wk, Wv, Wo);
    qkv_mma<<<dim3(HID / 128, MM / 128, 3), 128, PROJ_SMEM>>>(bq, bk, bv);
    vt_kernel<<<dim3(2, 64, NB * NH), 256>>>();
    attn_mma<<<dim3(SS / 128, NB * NH), 128, ATTN_SMEM>>>();
    oproj_mma<<<dim3(VD / 128, MM / 128), 128, PROJ_SMEM>>>(bo, out);
}

// round 11
// speedup vs baseline: 1.8258x; 1.7564x over previous
#include <cuda_runtime.h>
#include <cuda_fp16.h>
#include <math.h>
#include <cstdint>

#define NB 4
#define SS 2048
#define TD 768
#define HID 512
#define NH 8
#define HD 64
#define VD 768
#define MM (NB*SS)   // 8192

// Scratch (all operands fp16; accumulation fp32)
__device__ __half g_Q[NB*NH*SS*HD];   // [bh][s][d], pre-scaled 1/8
__device__ __half g_K[NB*NH*SS*HD];   // [bh][s][d]
__device__ __half g_V[NB*NH*SS*HD];   // [bh][s][d]
__device__ __half g_Vt[NB*NH*SS*HD];  // [bh][d][s]
__device__ __half g_A[MM*HID];        // attended, [b*s][h*d]
__device__ __half g_Xh[MM*TD];        // fp16 X
__device__ __half g_Wqt[HID*TD];      // fp16 TRANSPOSED weights [n][k]
__device__ __half g_Wkt[HID*TD];
__device__ __half g_Wvt[HID*TD];
__device__ __half g_Wot[VD*HID];

// ---------------------------------------------------------------------------
// Helpers (portable PTX, plain sm_103 target)
// ---------------------------------------------------------------------------
__device__ __forceinline__ uint32_t smem_u32(const void* p) {
    uint32_t a;
    asm("{ .reg .u64 t; cvta.to.shared.u64 t, %1; cvt.u32.u64 %0, t; }" : "=r"(a) : "l"(p));
    return a;
}
__device__ __forceinline__ uint32_t f2h2(float a, float b) {
    __half2 h = __floats2half2_rn(a, b);
    return *reinterpret_cast<uint32_t*>(&h);
}
__device__ __forceinline__ void cp16(uint32_t dst, const void* src) {
    asm volatile("cp.async.ca.shared.global [%0], [%1], 16;" :: "r"(dst), "l"(src));
}
#define CP_COMMIT() asm volatile("cp.async.commit_group;" ::: "memory")
#define CP_WAIT0()  asm volatile("cp.async.wait_group 0;" ::: "memory")

__device__ __forceinline__ void ldsm4(uint32_t* r, uint32_t a) {
    asm volatile("ldmatrix.sync.aligned.m8n8.x4.shared.b16 {%0,%1,%2,%3}, [%4];"
        : "=r"(r[0]), "=r"(r[1]), "=r"(r[2]), "=r"(r[3]) : "r"(a));
}
// A fragment (m16 x k16) from row-major [m][k] halves; stride in halves (≡8 mod 16)
__device__ __forceinline__ uint32_t a_addr_h(uint32_t base, int stride, int m0, int k0, int lane) {
    int sel = lane >> 3, r = lane & 7;
    return base + (((m0 + ((sel & 1) << 3) + r) * stride) + k0 + ((sel >> 1) << 3)) * 2;
}
// B fragments for two n-octets (n0..n0+15) x k16 from [n][k] halves -> {b0,b1,b0',b1'}
__device__ __forceinline__ uint32_t b_addr_h(uint32_t base, int stride, int n0, int k0, int lane) {
    int sel = lane >> 3, r = lane & 7;
    return base + (((n0 + ((sel >> 1) << 3) + r) * stride) + k0 + ((sel & 1) << 3)) * 2;
}

// m16n8k16 fp16 MMA, fp32 accum (g=lane>>2, tig=lane&3):
//  A: a0=[g][2tig..+1] a1=[g+8][2tig..] a2=[g][2tig+8..] a3=[g+8][2tig+8..]
//  B: b0=[k=2tig..][n=g] b1=[k=2tig+8..][n=g]
//  C: c0=[g][2tig] c1=[g][2tig+1] c2=[g+8][2tig] c3=[g+8][2tig+1]
__device__ __forceinline__ void mma16(float* c, const uint32_t* a, const uint32_t* b) {
    asm volatile(
        "mma.sync.aligned.m16n8k16.row.col.f32.f16.f16.f32 "
        "{%0,%1,%2,%3}, {%4,%5,%6,%7}, {%8,%9}, {%0,%1,%2,%3};"
        : "+f"(c[0]), "+f"(c[1]), "+f"(c[2]), "+f"(c[3])
        : "r"(a[0]), "r"(a[1]), "r"(a[2]), "r"(a[3]), "r"(b[0]), "r"(b[1]));
}

// ---------------------------------------------------------------------------
// Kernel 0a: convert X -> fp16
// ---------------------------------------------------------------------------
__global__ __launch_bounds__(256) void round_x(const float* __restrict__ X)
{
    const int stride = gridDim.x * blockDim.x;
    for (int i = blockIdx.x * blockDim.x + threadIdx.x; i < MM * TD / 4; i += stride) {
        float4 v = ((const float4*)X)[i];
        uint2 o;
        o.x = f2h2(v.x, v.y);
        o.y = f2h2(v.z, v.w);
        ((uint2*)g_Xh)[i] = o;
    }
}

// ---------------------------------------------------------------------------
// Kernel 0b: convert + TRANSPOSE weights [k][n] -> fp16 [n][k]
// ---------------------------------------------------------------------------
__global__ __launch_bounds__(256) void round_wt(
    const float* __restrict__ Wq, const float* __restrict__ Wk,
    const float* __restrict__ Wv, const float* __restrict__ Wo)
{
    __shared__ float tile[32][33];
    const int z = blockIdx.z;
    const float* W; __half* Wt; int K, N;
    if (z < 3) { K = TD; N = HID; W = (z == 0) ? Wq : (z == 1) ? Wk : Wv;
                 Wt = (z == 0) ? g_Wqt : (z == 1) ? g_Wkt : g_Wvt; }
    else       { K = HID; N = VD; W = Wo; Wt = g_Wot; }

    const int n0 = blockIdx.x * 32, k0 = blockIdx.y * 32;
    if (n0 >= N || k0 >= K) return;
    const int tx = threadIdx.x & 31, ty = threadIdx.x >> 5;   // 32 x 8
#pragma unroll
    for (int i = 0; i < 4; i++)
        tile[ty + 8 * i][tx] = W[(size_t)(k0 + ty + 8 * i) * N + n0 + tx];
    __syncthreads();
#pragma unroll
    for (int i = 0; i < 4; i++)
        Wt[(size_t)(n0 + ty + 8 * i) * K + k0 + tx] = __float2half_rn(tile[tx][ty + 8 * i]);
}

// ---------------------------------------------------------------------------
// Kernel 1.5: transpose V [bh][s][d] -> g_Vt [bh][d][s] (fp16)
// ---------------------------------------------------------------------------
__global__ __launch_bounds__(256) void vt_kernel()
{
    __shared__ __half tile[32][34];
    const int bh = blockIdx.z;
    const int d0 = blockIdx.x * 32, s0 = blockIdx.y * 32;
    const __half* V = g_V + (size_t)bh * SS * HD;
    __half* Vt = g_Vt + (size_t)bh * SS * HD;
    const int tx = threadIdx.x & 31, ty = threadIdx.x >> 5;
#pragma unroll
    for (int i = 0; i < 4; i++)
        tile[ty + 8 * i][tx] = V[(size_t)(s0 + ty + 8 * i) * HD + d0 + tx];
    __syncthreads();
#pragma unroll
    for (int i = 0; i < 4; i++)
        Vt[(size_t)(d0 + ty + 8 * i) * SS + s0 + tx] = tile[tx][ty + 8 * i];
}

// ===========================================================================
// Projection GEMM body (fp16). CTA 128(M) x 128(N), BK=64, 128 threads
// (4 warps), warp tile 64x64, m16n8k16. Both operands via ldmatrix.x4.
// smem halves: X[2][128][72] | Wt[2][128][72]  (73.7 KB total)
// ===========================================================================
#define PX0 0
#define PX1 9216
#define PW0 18432
#define PW1 27648
#define PROJ_SMEM (36864 * 2)

__device__ __forceinline__ void proj_issue(
    uint32_t sb, int buf, int kt,
    const __half* __restrict__ A, int lda,
    const __half* __restrict__ Wt, int ldw,
    int m0, int n0, int t)
{
    uint32_t xd = sb + (buf ? PX1 : PX0) * 2;
#pragma unroll
    for (int it = 0; it < 8; it++) {
        int i = t + it * 128;
        int r = i >> 3, fg = i & 7;
        cp16(xd + (r * 72 + fg * 8) * 2, &A[(size_t)(m0 + r) * lda + kt + fg * 8]);
    }
    uint32_t wd = sb + (buf ? PW1 : PW0) * 2;
#pragma unroll
    for (int it = 0; it < 8; it++) {
        int i = t + it * 128;
        int r = i >> 3, fg = i & 7;
        cp16(wd + (r * 72 + fg * 8) * 2, &Wt[(size_t)(n0 + r) * ldw + kt + fg * 8]);
    }
}

__device__ __forceinline__ void proj_body(
    uint32_t sb,
    const __half* __restrict__ A, int lda,
    const __half* __restrict__ Wt, int ldw,
    int kdim, int m0, int n0, float acc[4][8][4])
{
    const int t = threadIdx.x;
    const int w = t >> 5, lane = t & 31;
    const int mw = (w >> 1) * 64, nw = (w & 1) * 64;

#pragma unroll
    for (int mi = 0; mi < 4; mi++)
#pragma unroll
        for (int nj = 0; nj < 8; nj++)
#pragma unroll
            for (int r = 0; r < 4; r++) acc[mi][nj][r] = 0.f;

    const int nc = kdim >> 6;
    proj_issue(sb, 0, 0, A, lda, Wt, ldw, m0, n0, t);
    CP_COMMIT();

    for (int c = 0; c < nc; c++) {
        CP_WAIT0();
        __syncthreads();
        if (c + 1 < nc) {
            proj_issue(sb, (c + 1) & 1, (c + 1) << 6, A, lda, Wt, ldw, m0, n0, t);
            CP_COMMIT();
        }
        uint32_t xb = sb + ((c & 1) ? PX1 : PX0) * 2;
        uint32_t wb = sb + ((c & 1) ? PW1 : PW0) * 2;

#pragma unroll
        for (int ks = 0; ks < 4; ks++) {
            uint32_t af[4][4], bf[4][4];
#pragma unroll
            for (int mi = 0; mi < 4; mi++)
                ldsm4(af[mi], a_addr_h(xb, 72, mw + 16 * mi, ks * 16, lane));
#pragma unroll
            for (int p = 0; p < 4; p++)
                ldsm4(bf[p], b_addr_h(wb, 72, nw + p * 16, ks * 16, lane));
#pragma unroll
            for (int mi = 0; mi < 4; mi++)
#pragma unroll
                for (int p = 0; p < 4; p++) {
                    mma16(acc[mi][p * 2],     af[mi], bf[p]);
                    mma16(acc[mi][p * 2 + 1], af[mi], bf[p] + 2);
                }
        }
    }
}

// ---------------------------------------------------------------------------
// Kernel 1: fused QKV projection -> fp16 [bh][s][d]; Q pre-scaled 1/8 (exact)
// ---------------------------------------------------------------------------
__global__ __launch_bounds__(128) void qkv_mma(
    const float* __restrict__ bq, const float* __restrict__ bk,
    const float* __restrict__ bv)
{
    extern __shared__ __half smh[];
    uint32_t sb = smem_u32(smh);

    const int z = blockIdx.z;
    const __half* Wt  = (z == 0) ? g_Wqt : (z == 1) ? g_Wkt : g_Wvt;
    const float* bias = (z == 0) ? bq : (z == 1) ? bk : bv;
    __half* out       = (z == 0) ? g_Q : (z == 1) ? g_K : g_V;

    const int m0 = blockIdx.y * 128;
    const int n0 = blockIdx.x * 128;

    float acc[4][8][4];
    proj_body(sb, g_Xh, TD, Wt, TD, TD, m0, n0, acc);

    const int t = threadIdx.x;
    const int w = t >> 5, lane = t & 31, g = lane >> 2, tig = lane & 3;
    const int mw = (w >> 1) * 64, nw = (w & 1) * 64;
    const float qs = (z == 0) ? 0.125f : 1.0f;

#pragma unroll
    for (int mi = 0; mi < 4; mi++) {
        int r = m0 + mw + 16 * mi + g;
        int b_ = r >> 11, s_ = r & 2047;
#pragma unroll
        for (int nj = 0; nj < 8; nj++) {
            int cg = n0 + nw + nj * 8 + 2 * tig;
            int h = cg >> 6, d = cg & 63;
            __half* base0 = out + ((((size_t)(b_ * NH + h)) * SS + s_) << 6) + d;
            __half* base1 = base0 + (8 << 6);
            float2 bb = *(const float2*)&bias[cg];
            *(uint32_t*)base0 = f2h2((acc[mi][nj][0] + bb.x) * qs,
                                     (acc[mi][nj][1] + bb.y) * qs);
            *(uint32_t*)base1 = f2h2((acc[mi][nj][2] + bb.x) * qs,
                                     (acc[mi][nj][3] + bb.y) * qs);
        }
    }
}

// ---------------------------------------------------------------------------
// Kernel 3: output projection  out = g_A @ Wo + bo (fp32 output)
// ---------------------------------------------------------------------------
__global__ __launch_bounds__(128) void oproj_mma(
    const float* __restrict__ bo, float* __restrict__ out)
{
    extern __shared__ __half smh[];
    uint32_t sb = smem_u32(smh);
    const int m0 = blockIdx.y * 128;
    const int n0 = blockIdx.x * 128;

    float acc[4][8][4];
    proj_body(sb, g_A, HID, g_Wot, HID, HID, m0, n0, acc);

    const int t = threadIdx.x;
    const int w = t >> 5, lane = t & 31, g = lane >> 2, tig = lane & 3;
    const int mw = (w >> 1) * 64, nw = (w & 1) * 64;

#pragma unroll
    for (int mi = 0; mi < 4; mi++) {
        int r = m0 + mw + 16 * mi + g;
        float* base0 = out + (size_t)r * VD + n0 + nw;
        float* base1 = base0 + (size_t)8 * VD;
#pragma unroll
        for (int nj = 0; nj < 8; nj++) {
            int col = nj * 8 + 2 * tig;
            float2 bb = *(const float2*)&bo[n0 + nw + col];
            *(float2*)&base0[col] = make_float2(acc[mi][nj][0] + bb.x, acc[mi][nj][1] + bb.y);
            *(float2*)&base1[col] = make_float2(acc[mi][nj][2] + bb.x, acc[mi][nj][3] + bb.y);
        }
    }
}

// ===========================================================================
// Kernel 2: flash attention (fp16 operands). 128 threads (4 warps), q-tile
// 128 (32 rows/warp), key tile 64, m16n8k16. Q-frags in registers.
// smem halves: K[2][64][72] | Vt[2][64][72] | P[128][72]  (55.3 KB)
// ===========================================================================
#define AK0 0
#define AK1 4608
#define AV0 9216
#define AV1 13824
#define AP  18432
#define ATTN_SMEM ((18432 + 9216) * 2)
#define NIT (SS / 64)   // 32 key tiles

__device__ __forceinline__ void attn_issue(
    uint32_t sb, int buf, const __half* __restrict__ Kg,
    const __half* __restrict__ Vtg, int kt, int t)
{
    uint32_t kd = sb + (buf ? AK1 : AK0) * 2;
    uint32_t vd = sb + (buf ? AV1 : AV0) * 2;
    const __half* Kt = Kg + (size_t)kt * 64 * 64;
#pragma unroll
    for (int it = 0; it < 4; it++) {
        int i = t + it * 128;
        int r = i >> 3, fg = i & 7;
        cp16(kd + (r * 72 + fg * 8) * 2, &Kt[r * 64 + fg * 8]);
        cp16(vd + (r * 72 + fg * 8) * 2, &Vtg[(size_t)r * SS + kt * 64 + fg * 8]);
    }
}

__global__ __launch_bounds__(128) void attn_mma()
{
    extern __shared__ __half smh[];
    uint32_t sb = smem_u32(smh);
    const int t = threadIdx.x;
    const int w = t >> 5, lane = t & 31, g = lane >> 2, tig = lane & 3;
    const int qt = blockIdx.x, bh = blockIdx.y;
    const int mrow = w * 32;

    const __half* Qg  = g_Q  + (size_t)bh * SS * HD;
    const __half* Kg  = g_K  + (size_t)bh * SS * HD;
    const __half* Vtg = g_Vt + (size_t)bh * SS * HD;

    // Stage Q [128][72]h (pre-scaled) into the K region, extract frags, free.
#pragma unroll
    for (int it = 0; it < 8; it++) {
        int i = t + it * 128;
        int r = i >> 3, fg = i & 7;
        *(uint4*)&smh[r * 72 + fg * 8] =
            *(const uint4*)&Qg[(size_t)(qt * 128 + r) * 64 + fg * 8];
    }
    __syncthreads();
    uint32_t qa[4][2][4];
#pragma unroll
    for (int ks = 0; ks < 4; ks++) {
        ldsm4(qa[ks][0], a_addr_h(sb, 72, mrow, ks * 16, lane));
        ldsm4(qa[ks][1], a_addr_h(sb, 72, mrow + 16, ks * 16, lane));
    }
    __syncthreads();   // Q reads done; K/V region may be overwritten

    attn_issue(sb, 0, Kg, Vtg, 0, t);
    CP_COMMIT();

    float o[2][8][4];
#pragma unroll
    for (int mt = 0; mt < 2; mt++)
#pragma unroll
        for (int nj = 0; nj < 8; nj++)
#pragma unroll
            for (int r = 0; r < 4; r++) o[mt][nj][r] = 0.f;
    float mr[2][2] = {{-1e30f, -1e30f}, {-1e30f, -1e30f}};
    float lr[2][2] = {{0.f, 0.f}, {0.f, 0.f}};

    for (int kt = 0; kt < NIT; kt++) {
        CP_WAIT0();
        __syncthreads();
        if (kt + 1 < NIT) {
            attn_issue(sb, (kt + 1) & 1, Kg, Vtg, kt + 1, t);
            CP_COMMIT();
        }
        uint32_t kb = sb + ((kt & 1) ? AK1 : AK0) * 2;

        // S = Q K^T (pre-scaled), 32 rows x 64 keys per warp
        float s[2][8][4];
#pragma unroll
        for (int mt = 0; mt < 2; mt++)
#pragma unroll
            for (int nj = 0; nj < 8; nj++)
#pragma unroll
                for (int r = 0; r < 4; r++) s[mt][nj][r] = 0.f;

#pragma unroll
        for (int ks = 0; ks < 4; ks++)
#pragma unroll
            for (int p = 0; p < 4; p++) {
                uint32_t bf[4];
                ldsm4(bf, b_addr_h(kb, 72, p * 16, ks * 16, lane));
                mma16(s[0][p * 2],     qa[ks][0], bf);
                mma16(s[0][p * 2 + 1], qa[ks][0], bf + 2);
                mma16(s[1][p * 2],     qa[ks][1], bf);
                mma16(s[1][p * 2 + 1], qa[ks][1], bf + 2);
            }

        // Online softmax
        float corr[2][2];
#pragma unroll
        for (int mt = 0; mt < 2; mt++) {
            float mx0 = mr[mt][0], mx1 = mr[mt][1];
#pragma unroll
            for (int nj = 0; nj < 8; nj++) {
                mx0 = fmaxf(mx0, fmaxf(s[mt][nj][0], s[mt][nj][1]));
                mx1 = fmaxf(mx1, fmaxf(s[mt][nj][2], s[mt][nj][3]));
            }
            mx0 = fmaxf(mx0, __shfl_xor_sync(0xffffffffu, mx0, 1));
            mx0 = fmaxf(mx0, __shfl_xor_sync(0xffffffffu, mx0, 2));
            mx1 = fmaxf(mx1, __shfl_xor_sync(0xffffffffu, mx1, 1));
            mx1 = fmaxf(mx1, __shfl_xor_sync(0xffffffffu, mx1, 2));

            corr[mt][0] = __expf(mr[mt][0] - mx0);
            corr[mt][1] = __expf(mr[mt][1] - mx1);
            float ls0 = 0.f, ls1 = 0.f;
            int row0 = mrow + 16 * mt + g;
#pragma unroll
            for (int nj = 0; nj < 8; nj++) {
                float p0 = __expf(s[mt][nj][0] - mx0);
                float p1 = __expf(s[mt][nj][1] - mx0);
                float p2 = __expf(s[mt][nj][2] - mx1);
                float p3 = __expf(s[mt][nj][3] - mx1);
                ls0 += p0 + p1;
                ls1 += p2 + p3;
                *(uint32_t*)&smh[AP + row0 * 72 + nj * 8 + 2 * tig] = f2h2(p0, p1);
                *(uint32_t*)&smh[AP + (row0 + 8) * 72 + nj * 8 + 2 * tig] = f2h2(p2, p3);
            }
            ls0 += __shfl_xor_sync(0xffffffffu, ls0, 1);
            ls0 += __shfl_xor_sync(0xffffffffu, ls0, 2);
            ls1 += __shfl_xor_sync(0xffffffffu, ls1, 1);
            ls1 += __shfl_xor_sync(0xffffffffu, ls1, 2);
            lr[mt][0] = lr[mt][0] * corr[mt][0] + ls0;
            lr[mt][1] = lr[mt][1] * corr[mt][1] + ls1;
            mr[mt][0] = mx0; mr[mt][1] = mx1;

#pragma unroll
            for (int nj = 0; nj < 8; nj++) {
                o[mt][nj][0] *= corr[mt][0]; o[mt][nj][1] *= corr[mt][0];
                o[mt][nj][2] *= corr[mt][1]; o[mt][nj][3] *= corr[mt][1];
            }
        }
        __syncwarp();   // P rows are warp-private

        // O += P V   (A: P-frags; B: Vt [d][s])
        uint32_t pb = sb + AP * 2;
        uint32_t vb = sb + ((kt & 1) ? AV1 : AV0) * 2;
#pragma unroll
        for (int ks = 0; ks < 4; ks++) {
            uint32_t pa0[4], pa1[4];
            ldsm4(pa0, a_addr_h(pb, 72, mrow, ks * 16, lane));
            ldsm4(pa1, a_addr_h(pb, 72, mrow + 16, ks * 16, lane));
#pragma unroll
            for (int p = 0; p < 4; p++) {
                uint32_t bf[4];
                ldsm4(bf, b_addr_h(vb, 72, p * 16, ks * 16, lane));
                mma16(o[0][p * 2],     pa0, bf);
                mma16(o[0][p * 2 + 1], pa0, bf + 2);
                mma16(o[1][p * 2],     pa1, bf);
                mma16(o[1][p * 2 + 1], pa1, bf + 2);
            }
        }
    }

    // Epilogue: normalize, write g_A (fp16) [b*s][h*64]
    const int b_ = bh >> 3, h = bh & 7;
#pragma unroll
    for (int mt = 0; mt < 2; mt++) {
        float inv0 = 1.f / lr[mt][0], inv1 = 1.f / lr[mt][1];
        int r0 = qt * 128 + mrow + 16 * mt + g;
        __half* p0 = g_A + ((size_t)(b_ * SS + r0)) * HID + h * 64;
        __half* p1 = p0 + (size_t)8 * HID;
#pragma unroll
        for (int nj = 0; nj < 8; nj++) {
            *(uint32_t*)&p0[nj * 8 + 2 * tig] =
                f2h2(o[mt][nj][0] * inv0, o[mt][nj][1] * inv0);
            *(uint32_t*)&p1[nj * 8 + 2 * tig] =
                f2h2(o[mt][nj][2] * inv1, o[mt][nj][3] * inv1);
        }
    }
}

// ===========================================================================
extern "C" void kernel_launch(void* const* d_in, const int* in_sizes, int n_in,
                              void* d_out, int out_size)
{
    const float* X  = (const float*)d_in[0];
    const float* Wq = (const float*)d_in[1];
    const float* bq = (const float*)d_in[2];
    const float* Wk = (const float*)d_in[3];
    const float* bk = (const float*)d_in[4];
    const float* Wv = (const float*)d_in[5];
    const float* bv = (const float*)d_in[6];
    const float* Wo = (const float*)d_in[7];
    const float* bo = (const float*)d_in[8];
    float* out = (float*)d_out;

    cudaFuncSetAttribute(qkv_mma,   cudaFuncAttributeMaxDynamicSharedMemorySize, PROJ_SMEM);
    cudaFuncSetAttribute(oproj_mma, cudaFuncAttributeMaxDynamicSharedMemorySize, PROJ_SMEM);
    cudaFuncSetAttribute(attn_mma,  cudaFuncAttributeMaxDynamicSharedMemorySize, ATTN_SMEM);

    round_x<<<592, 256>>>(X);
    round_wt<<<dim3(24, 24, 4), 256>>>(Wq, Wk, Wv, Wo);
    qkv_mma<<<dim3(HID / 128, MM / 128, 3), 128, PROJ_SMEM>>>(bq, bk, bv);
    vt_kernel<<<dim3(2, 64, NB * NH), 256>>>();
    attn_mma<<<dim3(SS / 128, NB * NH), 128, ATTN_SMEM>>>();
    oproj_mma<<<dim3(VD / 128, MM / 128), 128, PROJ_SMEM>>>(bo, out);
}

// round 12
// speedup vs baseline: 1.9244x; 1.0540x over previous
#include <cuda_runtime.h>
#include <cuda_fp16.h>
#include <math.h>
#include <cstdint>

#define NB 4
#define SS 2048
#define TD 768
#define HID 512
#define NH 8
#define HD 64
#define VD 768
#define MM (NB*SS)   // 8192

// Scratch (all operands fp16; accumulation fp32)
__device__ __half g_Q[NB*NH*SS*HD];   // [bh][s][d], pre-scaled 1/8
__device__ __half g_K[NB*NH*SS*HD];   // [bh][s][d]
__device__ __half g_Vt[NB*NH*SS*HD];  // [bh][d][s]  (written directly by qkv)
__device__ __half g_A[MM*HID];        // attended, [b*s][h*d]
__device__ __half g_Xh[MM*TD];        // fp16 X
__device__ __half g_Wqt[HID*TD];      // fp16 TRANSPOSED weights [n][k]
__device__ __half g_Wkt[HID*TD];
__device__ __half g_Wvt[HID*TD];
__device__ __half g_Wot[VD*HID];

// ---------------------------------------------------------------------------
// Helpers (portable PTX, plain sm_103 target)
// ---------------------------------------------------------------------------
__device__ __forceinline__ uint32_t smem_u32(const void* p) {
    uint32_t a;
    asm("{ .reg .u64 t; cvta.to.shared.u64 t, %1; cvt.u32.u64 %0, t; }" : "=r"(a) : "l"(p));
    return a;
}
__device__ __forceinline__ uint32_t f2h2(float a, float b) {
    __half2 h = __floats2half2_rn(a, b);
    return *reinterpret_cast<uint32_t*>(&h);
}
__device__ __forceinline__ void cp16(uint32_t dst, const void* src) {
    asm volatile("cp.async.ca.shared.global [%0], [%1], 16;" :: "r"(dst), "l"(src));
}
#define CP_COMMIT() asm volatile("cp.async.commit_group;" ::: "memory")
#define CP_WAIT0()  asm volatile("cp.async.wait_group 0;" ::: "memory")

__device__ __forceinline__ void ldsm4(uint32_t* r, uint32_t a) {
    asm volatile("ldmatrix.sync.aligned.m8n8.x4.shared.b16 {%0,%1,%2,%3}, [%4];"
        : "=r"(r[0]), "=r"(r[1]), "=r"(r[2]), "=r"(r[3]) : "r"(a));
}
// A fragment (m16 x k16) from row-major [m][k] halves; stride in halves
__device__ __forceinline__ uint32_t a_addr_h(uint32_t base, int stride, int m0, int k0, int lane) {
    int sel = lane >> 3, r = lane & 7;
    return base + (((m0 + ((sel & 1) << 3) + r) * stride) + k0 + ((sel >> 1) << 3)) * 2;
}
// B fragments for two n-octets (n0..n0+15) x k16 from [n][k] halves
__device__ __forceinline__ uint32_t b_addr_h(uint32_t base, int stride, int n0, int k0, int lane) {
    int sel = lane >> 3, r = lane & 7;
    return base + (((n0 + ((sel >> 1) << 3) + r) * stride) + k0 + ((sel & 1) << 3)) * 2;
}

// m16n8k16 fp16 MMA, fp32 accum (g=lane>>2, tig=lane&3):
//  A: a0=[g][2tig,+1] a1=[g+8][2tig,+1] a2=[g][2tig+8,+1] a3=[g+8][2tig+8,+1]
//  C: c0=[g][2tig] c1=[g][2tig+1] c2=[g+8][2tig] c3=[g+8][2tig+1]
__device__ __forceinline__ void mma16(float* c, const uint32_t* a, const uint32_t* b) {
    asm volatile(
        "mma.sync.aligned.m16n8k16.row.col.f32.f16.f16.f32 "
        "{%0,%1,%2,%3}, {%4,%5,%6,%7}, {%8,%9}, {%0,%1,%2,%3};"
        : "+f"(c[0]), "+f"(c[1]), "+f"(c[2]), "+f"(c[3])
        : "r"(a[0]), "r"(a[1]), "r"(a[2]), "r"(a[3]), "r"(b[0]), "r"(b[1]));
}

// ---------------------------------------------------------------------------
// Kernel 0a: convert X -> fp16
// ---------------------------------------------------------------------------
__global__ __launch_bounds__(256) void round_x(const float* __restrict__ X)
{
    const int stride = gridDim.x * blockDim.x;
    for (int i = blockIdx.x * blockDim.x + threadIdx.x; i < MM * TD / 4; i += stride) {
        float4 v = ((const float4*)X)[i];
        uint2 o;
        o.x = f2h2(v.x, v.y);
        o.y = f2h2(v.z, v.w);
        ((uint2*)g_Xh)[i] = o;
    }
}

// ---------------------------------------------------------------------------
// Kernel 0b: convert + TRANSPOSE weights [k][n] -> fp16 [n][k]
// ---------------------------------------------------------------------------
__global__ __launch_bounds__(256) void round_wt(
    const float* __restrict__ Wq, const float* __restrict__ Wk,
    const float* __restrict__ Wv, const float* __restrict__ Wo)
{
    __shared__ float tile[32][33];
    const int z = blockIdx.z;
    const float* W; __half* Wt; int K, N;
    if (z < 3) { K = TD; N = HID; W = (z == 0) ? Wq : (z == 1) ? Wk : Wv;
                 Wt = (z == 0) ? g_Wqt : (z == 1) ? g_Wkt : g_Wvt; }
    else       { K = HID; N = VD; W = Wo; Wt = g_Wot; }

    const int n0 = blockIdx.x * 32, k0 = blockIdx.y * 32;
    if (n0 >= N || k0 >= K) return;
    const int tx = threadIdx.x & 31, ty = threadIdx.x >> 5;   // 32 x 8
#pragma unroll
    for (int i = 0; i < 4; i++)
        tile[ty + 8 * i][tx] = W[(size_t)(k0 + ty + 8 * i) * N + n0 + tx];
    __syncthreads();
#pragma unroll
    for (int i = 0; i < 4; i++)
        Wt[(size_t)(n0 + ty + 8 * i) * K + k0 + tx] = __float2half_rn(tile[tx][ty + 8 * i]);
}

// ===========================================================================
// Projection GEMM body (fp16). CTA 128(M) x 128(N), BK=64, 128 threads
// (4 warps), warp tile 64x64, m16n8k16. Both operands via ldmatrix.x4.
// smem halves: X[2][128][72] | Wt[2][128][72]
// ===========================================================================
#define PX0 0
#define PX1 9216
#define PW0 18432
#define PW1 27648
#define PROJ_SMEM (36864 * 2)

__device__ __forceinline__ void proj_issue(
    uint32_t sb, int buf, int kt,
    const __half* __restrict__ A, int lda,
    const __half* __restrict__ Wt, int ldw,
    int m0, int n0, int t)
{
    uint32_t xd = sb + (buf ? PX1 : PX0) * 2;
#pragma unroll
    for (int it = 0; it < 8; it++) {
        int i = t + it * 128;
        int r = i >> 3, fg = i & 7;
        cp16(xd + (r * 72 + fg * 8) * 2, &A[(size_t)(m0 + r) * lda + kt + fg * 8]);
    }
    uint32_t wd = sb + (buf ? PW1 : PW0) * 2;
#pragma unroll
    for (int it = 0; it < 8; it++) {
        int i = t + it * 128;
        int r = i >> 3, fg = i & 7;
        cp16(wd + (r * 72 + fg * 8) * 2, &Wt[(size_t)(n0 + r) * ldw + kt + fg * 8]);
    }
}

__device__ __forceinline__ void proj_body(
    uint32_t sb,
    const __half* __restrict__ A, int lda,
    const __half* __restrict__ Wt, int ldw,
    int kdim, int m0, int n0, float acc[4][8][4])
{
    const int t = threadIdx.x;
    const int w = t >> 5, lane = t & 31;
    const int mw = (w >> 1) * 64, nw = (w & 1) * 64;

#pragma unroll
    for (int mi = 0; mi < 4; mi++)
#pragma unroll
        for (int nj = 0; nj < 8; nj++)
#pragma unroll
            for (int r = 0; r < 4; r++) acc[mi][nj][r] = 0.f;

    const int nc = kdim >> 6;
    proj_issue(sb, 0, 0, A, lda, Wt, ldw, m0, n0, t);
    CP_COMMIT();

    for (int c = 0; c < nc; c++) {
        CP_WAIT0();
        __syncthreads();
        if (c + 1 < nc) {
            proj_issue(sb, (c + 1) & 1, (c + 1) << 6, A, lda, Wt, ldw, m0, n0, t);
            CP_COMMIT();
        }
        uint32_t xb = sb + ((c & 1) ? PX1 : PX0) * 2;
        uint32_t wb = sb + ((c & 1) ? PW1 : PW0) * 2;

#pragma unroll
        for (int ks = 0; ks < 4; ks++) {
            uint32_t af[4][4], bf[4][4];
#pragma unroll
            for (int mi = 0; mi < 4; mi++)
                ldsm4(af[mi], a_addr_h(xb, 72, mw + 16 * mi, ks * 16, lane));
#pragma unroll
            for (int p = 0; p < 4; p++)
                ldsm4(bf[p], b_addr_h(wb, 72, nw + p * 16, ks * 16, lane));
#pragma unroll
            for (int mi = 0; mi < 4; mi++)
#pragma unroll
                for (int p = 0; p < 4; p++) {
                    mma16(acc[mi][p * 2],     af[mi], bf[p]);
                    mma16(acc[mi][p * 2 + 1], af[mi], bf[p] + 2);
                }
        }
    }
}

// ---------------------------------------------------------------------------
// Kernel 1: fused QKV projection. Q/K -> [bh][s][d] (Q pre-scaled 1/8);
// V written TRANSPOSED directly into g_Vt [bh][d][s] (vt kernel fused away).
// ---------------------------------------------------------------------------
__global__ __launch_bounds__(128) void qkv_mma(
    const float* __restrict__ bq, const float* __restrict__ bk,
    const float* __restrict__ bv)
{
    extern __shared__ __half smh[];
    uint32_t sb = smem_u32(smh);

    const int z = blockIdx.z;
    const __half* Wt  = (z == 0) ? g_Wqt : (z == 1) ? g_Wkt : g_Wvt;
    const float* bias = (z == 0) ? bq : (z == 1) ? bk : bv;

    const int m0 = blockIdx.y * 128;
    const int n0 = blockIdx.x * 128;

    float acc[4][8][4];
    proj_body(sb, g_Xh, TD, Wt, TD, TD, m0, n0, acc);

    const int t = threadIdx.x;
    const int w = t >> 5, lane = t & 31, g = lane >> 2, tig = lane & 3;
    const int mw = (w >> 1) * 64, nw = (w & 1) * 64;

    if (z < 2) {
        __half* out = (z == 0) ? g_Q : g_K;
        const float qs = (z == 0) ? 0.125f : 1.0f;
#pragma unroll
        for (int mi = 0; mi < 4; mi++) {
            int r = m0 + mw + 16 * mi + g;
            int b_ = r >> 11, s_ = r & 2047;
#pragma unroll
            for (int nj = 0; nj < 8; nj++) {
                int cg = n0 + nw + nj * 8 + 2 * tig;
                int h = cg >> 6, d = cg & 63;
                __half* base0 = out + ((((size_t)(b_ * NH + h)) * SS + s_) << 6) + d;
                __half* base1 = base0 + (8 << 6);
                float2 bb = *(const float2*)&bias[cg];
                *(uint32_t*)base0 = f2h2((acc[mi][nj][0] + bb.x) * qs,
                                         (acc[mi][nj][1] + bb.y) * qs);
                *(uint32_t*)base1 = f2h2((acc[mi][nj][2] + bb.x) * qs,
                                         (acc[mi][nj][3] + bb.y) * qs);
            }
        }
    } else {
        // V: scatter-store transposed into g_Vt [bh][d][s]
#pragma unroll
        for (int mi = 0; mi < 4; mi++) {
            int r = m0 + mw + 16 * mi + g;
            int b_ = r >> 11, s_ = r & 2047;
#pragma unroll
            for (int nj = 0; nj < 8; nj++) {
                int cg = n0 + nw + nj * 8 + 2 * tig;
                int h = cg >> 6, d = cg & 63;
                float2 bb = *(const float2*)&bias[cg];
                __half* vb0 = g_Vt + (size_t)(b_ * NH + h) * SS * HD + (size_t)d * SS;
                __half* vb1 = vb0 + SS;   // d+1
                vb0[s_]     = __float2half_rn(acc[mi][nj][0] + bb.x);
                vb1[s_]     = __float2half_rn(acc[mi][nj][1] + bb.y);
                vb0[s_ + 8] = __float2half_rn(acc[mi][nj][2] + bb.x);
                vb1[s_ + 8] = __float2half_rn(acc[mi][nj][3] + bb.y);
            }
        }
    }
}

// ---------------------------------------------------------------------------
// Kernel 3: output projection  out = g_A @ Wo + bo (fp32 output)
// ---------------------------------------------------------------------------
__global__ __launch_bounds__(128) void oproj_mma(
    const float* __restrict__ bo, float* __restrict__ out)
{
    extern __shared__ __half smh[];
    uint32_t sb = smem_u32(smh);
    const int m0 = blockIdx.y * 128;
    const int n0 = blockIdx.x * 128;

    float acc[4][8][4];
    proj_body(sb, g_A, HID, g_Wot, HID, HID, m0, n0, acc);

    const int t = threadIdx.x;
    const int w = t >> 5, lane = t & 31, g = lane >> 2, tig = lane & 3;
    const int mw = (w >> 1) * 64, nw = (w & 1) * 64;

#pragma unroll
    for (int mi = 0; mi < 4; mi++) {
        int r = m0 + mw + 16 * mi + g;
        float* base0 = out + (size_t)r * VD + n0 + nw;
        float* base1 = base0 + (size_t)8 * VD;
#pragma unroll
        for (int nj = 0; nj < 8; nj++) {
            int col = nj * 8 + 2 * tig;
            float2 bb = *(const float2*)&bo[n0 + nw + col];
            *(float2*)&base0[col] = make_float2(acc[mi][nj][0] + bb.x, acc[mi][nj][1] + bb.y);
            *(float2*)&base1[col] = make_float2(acc[mi][nj][2] + bb.x, acc[mi][nj][3] + bb.y);
        }
    }
}

// ===========================================================================
// Kernel 2: flash attention (fp16). 128 threads (4 warps), q-tile 128
// (32 rows/warp), key tile 64, m16n8k16. Q-frags in registers.
// FA-2 register P: the S C-fragment packs DIRECTLY into the PV A-fragment
// (half2 f2h2 of c-pairs) — P never touches smem.
// smem halves: K[2][64][72] | Vt[2][64][72]   (36.9 KB)
// ===========================================================================
#define AK0 0
#define AK1 4608
#define AV0 9216
#define AV1 13824
#define ATTN_SMEM (18432 * 2)
#define NIT (SS / 64)   // 32 key tiles

__device__ __forceinline__ void attn_issue(
    uint32_t sb, int buf, const __half* __restrict__ Kg,
    const __half* __restrict__ Vtg, int kt, int t)
{
    uint32_t kd = sb + (buf ? AK1 : AK0) * 2;
    uint32_t vd = sb + (buf ? AV1 : AV0) * 2;
    const __half* Kt = Kg + (size_t)kt * 64 * 64;
#pragma unroll
    for (int it = 0; it < 4; it++) {
        int i = t + it * 128;
        int r = i >> 3, fg = i & 7;
        cp16(kd + (r * 72 + fg * 8) * 2, &Kt[r * 64 + fg * 8]);
        cp16(vd + (r * 72 + fg * 8) * 2, &Vtg[(size_t)r * SS + kt * 64 + fg * 8]);
    }
}

__global__ __launch_bounds__(128) void attn_mma()
{
    extern __shared__ __half smh[];
    uint32_t sb = smem_u32(smh);
    const int t = threadIdx.x;
    const int w = t >> 5, lane = t & 31, g = lane >> 2;
    const int qt = blockIdx.x, bh = blockIdx.y;
    const int mrow = w * 32;

    const __half* Qg  = g_Q  + (size_t)bh * SS * HD;
    const __half* Kg  = g_K  + (size_t)bh * SS * HD;
    const __half* Vtg = g_Vt + (size_t)bh * SS * HD;

    // Stage Q [128][72]h (pre-scaled) into K region, extract frags, free.
#pragma unroll
    for (int it = 0; it < 8; it++) {
        int i = t + it * 128;
        int r = i >> 3, fg = i & 7;
        *(uint4*)&smh[r * 72 + fg * 8] =
            *(const uint4*)&Qg[(size_t)(qt * 128 + r) * 64 + fg * 8];
    }
    __syncthreads();
    uint32_t qa[4][2][4];
#pragma unroll
    for (int ks = 0; ks < 4; ks++) {
        ldsm4(qa[ks][0], a_addr_h(sb, 72, mrow, ks * 16, lane));
        ldsm4(qa[ks][1], a_addr_h(sb, 72, mrow + 16, ks * 16, lane));
    }
    __syncthreads();   // Q reads done; K/V region may be overwritten

    attn_issue(sb, 0, Kg, Vtg, 0, t);
    CP_COMMIT();

    float o[2][8][4];
#pragma unroll
    for (int mt = 0; mt < 2; mt++)
#pragma unroll
        for (int nj = 0; nj < 8; nj++)
#pragma unroll
            for (int r = 0; r < 4; r++) o[mt][nj][r] = 0.f;
    float mr[2][2] = {{-1e30f, -1e30f}, {-1e30f, -1e30f}};
    float lr[2][2] = {{0.f, 0.f}, {0.f, 0.f}};

    for (int kt = 0; kt < NIT; kt++) {
        CP_WAIT0();
        __syncthreads();
        if (kt + 1 < NIT) {
            attn_issue(sb, (kt + 1) & 1, Kg, Vtg, kt + 1, t);
            CP_COMMIT();
        }
        uint32_t kb = sb + ((kt & 1) ? AK1 : AK0) * 2;

        // S = Q K^T (pre-scaled), 32 rows x 64 keys per warp
        float s[2][8][4];
#pragma unroll
        for (int mt = 0; mt < 2; mt++)
#pragma unroll
            for (int nj = 0; nj < 8; nj++)
#pragma unroll
                for (int r = 0; r < 4; r++) s[mt][nj][r] = 0.f;

#pragma unroll
        for (int ks = 0; ks < 4; ks++)
#pragma unroll
            for (int p = 0; p < 4; p++) {
                uint32_t bf[4];
                ldsm4(bf, b_addr_h(kb, 72, p * 16, ks * 16, lane));
                mma16(s[0][p * 2],     qa[ks][0], bf);
                mma16(s[0][p * 2 + 1], qa[ks][0], bf + 2);
                mma16(s[1][p * 2],     qa[ks][1], bf);
                mma16(s[1][p * 2 + 1], qa[ks][1], bf + 2);
            }

        // Online softmax; exp results stay in s[] (registers)
        float corr[2][2];
#pragma unroll
        for (int mt = 0; mt < 2; mt++) {
            float mx0 = mr[mt][0], mx1 = mr[mt][1];
#pragma unroll
            for (int nj = 0; nj < 8; nj++) {
                mx0 = fmaxf(mx0, fmaxf(s[mt][nj][0], s[mt][nj][1]));
                mx1 = fmaxf(mx1, fmaxf(s[mt][nj][2], s[mt][nj][3]));
            }
            mx0 = fmaxf(mx0, __shfl_xor_sync(0xffffffffu, mx0, 1));
            mx0 = fmaxf(mx0, __shfl_xor_sync(0xffffffffu, mx0, 2));
            mx1 = fmaxf(mx1, __shfl_xor_sync(0xffffffffu, mx1, 1));
            mx1 = fmaxf(mx1, __shfl_xor_sync(0xffffffffu, mx1, 2));

            corr[mt][0] = __expf(mr[mt][0] - mx0);
            corr[mt][1] = __expf(mr[mt][1] - mx1);
            float ls0 = 0.f, ls1 = 0.f;
#pragma unroll
            for (int nj = 0; nj < 8; nj++) {
                float p0 = __expf(s[mt][nj][0] - mx0);
                float p1 = __expf(s[mt][nj][1] - mx0);
                float p2 = __expf(s[mt][nj][2] - mx1);
                float p3 = __expf(s[mt][nj][3] - mx1);
                ls0 += p0 + p1;
                ls1 += p2 + p3;
                s[mt][nj][0] = p0; s[mt][nj][1] = p1;
                s[mt][nj][2] = p2; s[mt][nj][3] = p3;
            }
            ls0 += __shfl_xor_sync(0xffffffffu, ls0, 1);
            ls0 += __shfl_xor_sync(0xffffffffu, ls0, 2);
            ls1 += __shfl_xor_sync(0xffffffffu, ls1, 1);
            ls1 += __shfl_xor_sync(0xffffffffu, ls1, 2);
            lr[mt][0] = lr[mt][0] * corr[mt][0] + ls0;
            lr[mt][1] = lr[mt][1] * corr[mt][1] + ls1;
            mr[mt][0] = mx0; mr[mt][1] = mx1;

#pragma unroll
            for (int nj = 0; nj < 8; nj++) {
                o[mt][nj][0] *= corr[mt][0]; o[mt][nj][1] *= corr[mt][0];
                o[mt][nj][2] *= corr[mt][1]; o[mt][nj][3] *= corr[mt][1];
            }
        }

        // O += P V. P A-fragments built directly from s[] (C-frag == A-frag):
        //  a0 = (c0,c1)[row g],  a1 = (c2,c3)[row g+8]  of key-octet 2ks
        //  a2,a3 = same from key-octet 2ks+1
        uint32_t vb = sb + ((kt & 1) ? AV1 : AV0) * 2;
#pragma unroll
        for (int ks = 0; ks < 4; ks++) {
            uint32_t pa0[4], pa1[4];
            pa0[0] = f2h2(s[0][2*ks][0],   s[0][2*ks][1]);
            pa0[1] = f2h2(s[0][2*ks][2],   s[0][2*ks][3]);
            pa0[2] = f2h2(s[0][2*ks+1][0], s[0][2*ks+1][1]);
            pa0[3] = f2h2(s[0][2*ks+1][2], s[0][2*ks+1][3]);
            pa1[0] = f2h2(s[1][2*ks][0],   s[1][2*ks][1]);
            pa1[1] = f2h2(s[1][2*ks][2],   s[1][2*ks][3]);
            pa1[2] = f2h2(s[1][2*ks+1][0], s[1][2*ks+1][1]);
            pa1[3] = f2h2(s[1][2*ks+1][2], s[1][2*ks+1][3]);
#pragma unroll
            for (int p = 0; p < 4; p++) {
                uint32_t bf[4];
                ldsm4(bf, b_addr_h(vb, 72, p * 16, ks * 16, lane));
                mma16(o[0][p * 2],     pa0, bf);
                mma16(o[0][p * 2 + 1], pa0, bf + 2);
                mma16(o[1][p * 2],     pa1, bf);
                mma16(o[1][p * 2 + 1], pa1, bf + 2);
            }
        }
    }

    // Epilogue: normalize, write g_A (fp16) [b*s][h*64]
    const int b_ = bh >> 3, h = bh & 7;
    const int tig = lane & 3;
#pragma unroll
    for (int mt = 0; mt < 2; mt++) {
        float inv0 = 1.f / lr[mt][0], inv1 = 1.f / lr[mt][1];
        int r0 = qt * 128 + mrow + 16 * mt + g;
        __half* p0 = g_A + ((size_t)(b_ * SS + r0)) * HID + h * 64;
        __half* p1 = p0 + (size_t)8 * HID;
#pragma unroll
        for (int nj = 0; nj < 8; nj++) {
            *(uint32_t*)&p0[nj * 8 + 2 * tig] =
                f2h2(o[mt][nj][0] * inv0, o[mt][nj][1] * inv0);
            *(uint32_t*)&p1[nj * 8 + 2 * tig] =
                f2h2(o[mt][nj][2] * inv1, o[mt][nj][3] * inv1);
        }
    }
}

// ===========================================================================
extern "C" void kernel_launch(void* const* d_in, const int* in_sizes, int n_in,
                              void* d_out, int out_size)
{
    const float* X  = (const float*)d_in[0];
    const float* Wq = (const float*)d_in[1];
    const float* bq = (const float*)d_in[2];
    const float* Wk = (const float*)d_in[3];
    const float* bk = (const float*)d_in[4];
    const float* Wv = (const float*)d_in[5];
    const float* bv = (const float*)d_in[6];
    const float* Wo = (const float*)d_in[7];
    const float* bo = (const float*)d_in[8];
    float* out = (float*)d_out;

    cudaFuncSetAttribute(qkv_mma,   cudaFuncAttributeMaxDynamicSharedMemorySize, PROJ_SMEM);
    cudaFuncSetAttribute(oproj_mma, cudaFuncAttributeMaxDynamicSharedMemorySize, PROJ_SMEM);
    cudaFuncSetAttribute(attn_mma,  cudaFuncAttributeMaxDynamicSharedMemorySize, ATTN_SMEM);

    round_x<<<592, 256>>>(X);
    round_wt<<<dim3(24, 24, 4), 256>>>(Wq, Wk, Wv, Wo);
    qkv_mma<<<dim3(HID / 128, MM / 128, 3), 128, PROJ_SMEM>>>(bq, bk, bv);
    attn_mma<<<dim3(SS / 128, NB * NH), 128, ATTN_SMEM>>>();
    oproj_mma<<<dim3(VD / 128, MM / 128), 128, PROJ_SMEM>>>(bo, out);
}

// round 13
// speedup vs baseline: 2.0460x; 1.0632x over previous
#include <cuda_runtime.h>
#include <cuda_fp16.h>
#include <math.h>
#include <cstdint>

#define NB 4
#define SS 2048
#define TD 768
#define HID 512
#define NH 8
#define HD 64
#define VD 768
#define MM (NB*SS)   // 8192

// Scratch (all operands fp16; accumulation fp32)
__device__ __half g_Q[NB*NH*SS*HD];   // [bh][s][d], pre-scaled log2e/8
__device__ __half g_K[NB*NH*SS*HD];   // [bh][s][d]
__device__ __half g_Vt[NB*NH*SS*HD];  // [bh][d][s]  (written directly by qkv)
__device__ __half g_A[MM*HID];        // attended, [b*s][h*d]
__device__ __half g_Xh[MM*TD];        // fp16 X
__device__ __half g_Wqt[HID*TD];      // fp16 TRANSPOSED weights [n][k]
__device__ __half g_Wkt[HID*TD];
__device__ __half g_Wvt[HID*TD];
__device__ __half g_Wot[VD*HID];

// ---------------------------------------------------------------------------
// Helpers (portable PTX, plain sm_103 target)
// ---------------------------------------------------------------------------
__device__ __forceinline__ uint32_t smem_u32(const void* p) {
    uint32_t a;
    asm("{ .reg .u64 t; cvta.to.shared.u64 t, %1; cvt.u32.u64 %0, t; }" : "=r"(a) : "l"(p));
    return a;
}
__device__ __forceinline__ uint32_t f2h2(float a, float b) {
    __half2 h = __floats2half2_rn(a, b);
    return *reinterpret_cast<uint32_t*>(&h);
}
// exp2 on a packed half2
__device__ __forceinline__ uint32_t ex2_h2(uint32_t x) {
    uint32_t y;
    asm("ex2.approx.f16x2 %0, %1;" : "=r"(y) : "r"(x));
    return y;
}
__device__ __forceinline__ void cp16(uint32_t dst, const void* src) {
    asm volatile("cp.async.ca.shared.global [%0], [%1], 16;" :: "r"(dst), "l"(src));
}
#define CP_COMMIT() asm volatile("cp.async.commit_group;" ::: "memory")
#define CP_WAIT0()  asm volatile("cp.async.wait_group 0;" ::: "memory")

__device__ __forceinline__ void ldsm4(uint32_t* r, uint32_t a) {
    asm volatile("ldmatrix.sync.aligned.m8n8.x4.shared.b16 {%0,%1,%2,%3}, [%4];"
        : "=r"(r[0]), "=r"(r[1]), "=r"(r[2]), "=r"(r[3]) : "r"(a));
}
__device__ __forceinline__ uint32_t a_addr_h(uint32_t base, int stride, int m0, int k0, int lane) {
    int sel = lane >> 3, r = lane & 7;
    return base + (((m0 + ((sel & 1) << 3) + r) * stride) + k0 + ((sel >> 1) << 3)) * 2;
}
__device__ __forceinline__ uint32_t b_addr_h(uint32_t base, int stride, int n0, int k0, int lane) {
    int sel = lane >> 3, r = lane & 7;
    return base + (((n0 + ((sel >> 1) << 3) + r) * stride) + k0 + ((sel & 1) << 3)) * 2;
}

// m16n8k16 fp16 MMA, fp32 accum (g=lane>>2, tig=lane&3):
//  A: a0=[g][2tig,+1] a1=[g+8][2tig,+1] a2=[g][2tig+8,+1] a3=[g+8][2tig+8,+1]
//  C: c0=[g][2tig] c1=[g][2tig+1] c2=[g+8][2tig] c3=[g+8][2tig+1]
__device__ __forceinline__ void mma16(float* c, const uint32_t* a, const uint32_t* b) {
    asm volatile(
        "mma.sync.aligned.m16n8k16.row.col.f32.f16.f16.f32 "
        "{%0,%1,%2,%3}, {%4,%5,%6,%7}, {%8,%9}, {%0,%1,%2,%3};"
        : "+f"(c[0]), "+f"(c[1]), "+f"(c[2]), "+f"(c[3])
        : "r"(a[0]), "r"(a[1]), "r"(a[2]), "r"(a[3]), "r"(b[0]), "r"(b[1]));
}

// ---------------------------------------------------------------------------
// Kernel 0a: convert X -> fp16
// ---------------------------------------------------------------------------
__global__ __launch_bounds__(256) void round_x(const float* __restrict__ X)
{
    const int stride = gridDim.x * blockDim.x;
    for (int i = blockIdx.x * blockDim.x + threadIdx.x; i < MM * TD / 4; i += stride) {
        float4 v = ((const float4*)X)[i];
        uint2 o;
        o.x = f2h2(v.x, v.y);
        o.y = f2h2(v.z, v.w);
        ((uint2*)g_Xh)[i] = o;
    }
}

// ---------------------------------------------------------------------------
// Kernel 0b: convert + TRANSPOSE weights [k][n] -> fp16 [n][k]
// ---------------------------------------------------------------------------
__global__ __launch_bounds__(256) void round_wt(
    const float* __restrict__ Wq, const float* __restrict__ Wk,
    const float* __restrict__ Wv, const float* __restrict__ Wo)
{
    __shared__ float tile[32][33];
    const int z = blockIdx.z;
    const float* W; __half* Wt; int K, N;
    if (z < 3) { K = TD; N = HID; W = (z == 0) ? Wq : (z == 1) ? Wk : Wv;
                 Wt = (z == 0) ? g_Wqt : (z == 1) ? g_Wkt : g_Wvt; }
    else       { K = HID; N = VD; W = Wo; Wt = g_Wot; }

    const int n0 = blockIdx.x * 32, k0 = blockIdx.y * 32;
    if (n0 >= N || k0 >= K) return;
    const int tx = threadIdx.x & 31, ty = threadIdx.x >> 5;
#pragma unroll
    for (int i = 0; i < 4; i++)
        tile[ty + 8 * i][tx] = W[(size_t)(k0 + ty + 8 * i) * N + n0 + tx];
    __syncthreads();
#pragma unroll
    for (int i = 0; i < 4; i++)
        Wt[(size_t)(n0 + ty + 8 * i) * K + k0 + tx] = __float2half_rn(tile[tx][ty + 8 * i]);
}

// ===========================================================================
// Projection GEMM body (fp16). CTA 128x128, BK=64, 128 threads, warp 64x64.
// smem halves: X[2][128][72] | Wt[2][128][72]
// ===========================================================================
#define PX0 0
#define PX1 9216
#define PW0 18432
#define PW1 27648
#define PROJ_SMEM (36864 * 2)

__device__ __forceinline__ void proj_issue(
    uint32_t sb, int buf, int kt,
    const __half* __restrict__ A, int lda,
    const __half* __restrict__ Wt, int ldw,
    int m0, int n0, int t)
{
    uint32_t xd = sb + (buf ? PX1 : PX0) * 2;
#pragma unroll
    for (int it = 0; it < 8; it++) {
        int i = t + it * 128;
        int r = i >> 3, fg = i & 7;
        cp16(xd + (r * 72 + fg * 8) * 2, &A[(size_t)(m0 + r) * lda + kt + fg * 8]);
    }
    uint32_t wd = sb + (buf ? PW1 : PW0) * 2;
#pragma unroll
    for (int it = 0; it < 8; it++) {
        int i = t + it * 128;
        int r = i >> 3, fg = i & 7;
        cp16(wd + (r * 72 + fg * 8) * 2, &Wt[(size_t)(n0 + r) * ldw + kt + fg * 8]);
    }
}

__device__ __forceinline__ void proj_body(
    uint32_t sb,
    const __half* __restrict__ A, int lda,
    const __half* __restrict__ Wt, int ldw,
    int kdim, int m0, int n0, float acc[4][8][4])
{
    const int t = threadIdx.x;
    const int w = t >> 5, lane = t & 31;
    const int mw = (w >> 1) * 64, nw = (w & 1) * 64;

#pragma unroll
    for (int mi = 0; mi < 4; mi++)
#pragma unroll
        for (int nj = 0; nj < 8; nj++)
#pragma unroll
            for (int r = 0; r < 4; r++) acc[mi][nj][r] = 0.f;

    const int nc = kdim >> 6;
    proj_issue(sb, 0, 0, A, lda, Wt, ldw, m0, n0, t);
    CP_COMMIT();

    for (int c = 0; c < nc; c++) {
        CP_WAIT0();
        __syncthreads();
        if (c + 1 < nc) {
            proj_issue(sb, (c + 1) & 1, (c + 1) << 6, A, lda, Wt, ldw, m0, n0, t);
            CP_COMMIT();
        }
        uint32_t xb = sb + ((c & 1) ? PX1 : PX0) * 2;
        uint32_t wb = sb + ((c & 1) ? PW1 : PW0) * 2;

#pragma unroll
        for (int ks = 0; ks < 4; ks++) {
            uint32_t af[4][4], bf[4][4];
#pragma unroll
            for (int mi = 0; mi < 4; mi++)
                ldsm4(af[mi], a_addr_h(xb, 72, mw + 16 * mi, ks * 16, lane));
#pragma unroll
            for (int p = 0; p < 4; p++)
                ldsm4(bf[p], b_addr_h(wb, 72, nw + p * 16, ks * 16, lane));
#pragma unroll
            for (int mi = 0; mi < 4; mi++)
#pragma unroll
                for (int p = 0; p < 4; p++) {
                    mma16(acc[mi][p * 2],     af[mi], bf[p]);
                    mma16(acc[mi][p * 2 + 1], af[mi], bf[p] + 2);
                }
        }
    }
}

// ---------------------------------------------------------------------------
// Kernel 1: fused QKV projection. Q scaled by log2e/8 (scores in log2 domain).
// V written TRANSPOSED directly into g_Vt [bh][d][s].
// ---------------------------------------------------------------------------
__global__ __launch_bounds__(128) void qkv_mma(
    const float* __restrict__ bq, const float* __restrict__ bk,
    const float* __restrict__ bv)
{
    extern __shared__ __half smh[];
    uint32_t sb = smem_u32(smh);

    const int z = blockIdx.z;
    const __half* Wt  = (z == 0) ? g_Wqt : (z == 1) ? g_Wkt : g_Wvt;
    const float* bias = (z == 0) ? bq : (z == 1) ? bk : bv;

    const int m0 = blockIdx.y * 128;
    const int n0 = blockIdx.x * 128;

    float acc[4][8][4];
    proj_body(sb, g_Xh, TD, Wt, TD, TD, m0, n0, acc);

    const int t = threadIdx.x;
    const int w = t >> 5, lane = t & 31, g = lane >> 2, tig = lane & 3;
    const int mw = (w >> 1) * 64, nw = (w & 1) * 64;

    if (z < 2) {
        __half* out = (z == 0) ? g_Q : g_K;
        const float qs = (z == 0) ? 0.18033688011112042f : 1.0f;  // log2e/8
#pragma unroll
        for (int mi = 0; mi < 4; mi++) {
            int r = m0 + mw + 16 * mi + g;
            int b_ = r >> 11, s_ = r & 2047;
#pragma unroll
            for (int nj = 0; nj < 8; nj++) {
                int cg = n0 + nw + nj * 8 + 2 * tig;
                int h = cg >> 6, d = cg & 63;
                __half* base0 = out + ((((size_t)(b_ * NH + h)) * SS + s_) << 6) + d;
                __half* base1 = base0 + (8 << 6);
                float2 bb = *(const float2*)&bias[cg];
                *(uint32_t*)base0 = f2h2((acc[mi][nj][0] + bb.x) * qs,
                                         (acc[mi][nj][1] + bb.y) * qs);
                *(uint32_t*)base1 = f2h2((acc[mi][nj][2] + bb.x) * qs,
                                         (acc[mi][nj][3] + bb.y) * qs);
            }
        }
    } else {
#pragma unroll
        for (int mi = 0; mi < 4; mi++) {
            int r = m0 + mw + 16 * mi + g;
            int b_ = r >> 11, s_ = r & 2047;
#pragma unroll
            for (int nj = 0; nj < 8; nj++) {
                int cg = n0 + nw + nj * 8 + 2 * tig;
                int h = cg >> 6, d = cg & 63;
                float2 bb = *(const float2*)&bias[cg];
                __half* vb0 = g_Vt + (size_t)(b_ * NH + h) * SS * HD + (size_t)d * SS;
                __half* vb1 = vb0 + SS;
                vb0[s_]     = __float2half_rn(acc[mi][nj][0] + bb.x);
                vb1[s_]     = __float2half_rn(acc[mi][nj][1] + bb.y);
                vb0[s_ + 8] = __float2half_rn(acc[mi][nj][2] + bb.x);
                vb1[s_ + 8] = __float2half_rn(acc[mi][nj][3] + bb.y);
            }
        }
    }
}

// ---------------------------------------------------------------------------
// Kernel 3: output projection  out = g_A @ Wo + bo (fp32 output)
// ---------------------------------------------------------------------------
__global__ __launch_bounds__(128) void oproj_mma(
    const float* __restrict__ bo, float* __restrict__ out)
{
    extern __shared__ __half smh[];
    uint32_t sb = smem_u32(smh);
    const int m0 = blockIdx.y * 128;
    const int n0 = blockIdx.x * 128;

    float acc[4][8][4];
    proj_body(sb, g_A, HID, g_Wot, HID, HID, m0, n0, acc);

    const int t = threadIdx.x;
    const int w = t >> 5, lane = t & 31, g = lane >> 2, tig = lane & 3;
    const int mw = (w >> 1) * 64, nw = (w & 1) * 64;

#pragma unroll
    for (int mi = 0; mi < 4; mi++) {
        int r = m0 + mw + 16 * mi + g;
        float* base0 = out + (size_t)r * VD + n0 + nw;
        float* base1 = base0 + (size_t)8 * VD;
#pragma unroll
        for (int nj = 0; nj < 8; nj++) {
            int col = nj * 8 + 2 * tig;
            float2 bb = *(const float2*)&bo[n0 + nw + col];
            *(float2*)&base0[col] = make_float2(acc[mi][nj][0] + bb.x, acc[mi][nj][1] + bb.y);
            *(float2*)&base1[col] = make_float2(acc[mi][nj][2] + bb.x, acc[mi][nj][3] + bb.y);
        }
    }
}

// ===========================================================================
// Kernel 2: flash attention (fp16). 128 threads (4 warps), q-tile 128
// (32 rows/warp), key tile 64, m16n8k16. Scores in log2 domain.
// - exp via ex2.approx.f16x2 -> packed half2 IS the PV A-fragment
// - row-sum l via ONES-COLUMN MMA (Vt row d=64 = 1s): l is output col 64,
//   rescaled by corr like O. No ls FADD chain, no lr bookkeeping.
// smem halves: K[2][64][72] | Vt[2][80][72] (rows 64..79: ones/zeros const)
// ===========================================================================
#define AK0 0
#define AK1 4608
#define AV0 9216
#define AV1 14976
#define ATTN_SMEM (20736 * 2)
#define NIT (SS / 64)   // 32 key tiles

__device__ __forceinline__ void attn_issue(
    uint32_t sb, int buf, const __half* __restrict__ Kg,
    const __half* __restrict__ Vtg, int kt, int t)
{
    uint32_t kd = sb + (buf ? AK1 : AK0) * 2;
    uint32_t vd = sb + (buf ? AV1 : AV0) * 2;
    const __half* Kt = Kg + (size_t)kt * 64 * 64;
#pragma unroll
    for (int it = 0; it < 4; it++) {
        int i = t + it * 128;
        int r = i >> 3, fg = i & 7;
        cp16(kd + (r * 72 + fg * 8) * 2, &Kt[r * 64 + fg * 8]);
        cp16(vd + (r * 72 + fg * 8) * 2, &Vtg[(size_t)r * SS + kt * 64 + fg * 8]);
    }
}

__global__ __launch_bounds__(128) void attn_mma()
{
    extern __shared__ __half smh[];
    uint32_t sb = smem_u32(smh);
    const int t = threadIdx.x;
    const int w = t >> 5, lane = t & 31, g = lane >> 2;
    const int qt = blockIdx.x, bh = blockIdx.y;
    const int mrow = w * 32;

    const __half* Qg  = g_Q  + (size_t)bh * SS * HD;
    const __half* Kg  = g_K  + (size_t)bh * SS * HD;
    const __half* Vtg = g_Vt + (size_t)bh * SS * HD;

    // Stage Q (pre-scaled, log2 domain) into K region, extract frags, free.
#pragma unroll
    for (int it = 0; it < 8; it++) {
        int i = t + it * 128;
        int r = i >> 3, fg = i & 7;
        *(uint4*)&smh[r * 72 + fg * 8] =
            *(const uint4*)&Qg[(size_t)(qt * 128 + r) * 64 + fg * 8];
    }
    __syncthreads();
    uint32_t qa[4][2][4];
#pragma unroll
    for (int ks = 0; ks < 4; ks++) {
        ldsm4(qa[ks][0], a_addr_h(sb, 72, mrow, ks * 16, lane));
        ldsm4(qa[ks][1], a_addr_h(sb, 72, mrow + 16, ks * 16, lane));
    }
    __syncthreads();   // Q reads done; K/V region may be overwritten

    // Init the constant ones/zeros rows 64..79 of BOTH V buffers.
    // cp.async only ever writes rows 0..63, so these persist.
    {
        const __half one = __float2half_rn(1.0f);
        const __half zero = __float2half_rn(0.0f);
        for (int i = t; i < 2 * 16 * 72; i += 128) {
            int buf = i / (16 * 72);
            int rem = i % (16 * 72);
            int row = 64 + rem / 72, col = rem % 72;
            smh[(buf ? AV1 : AV0) + row * 72 + col] = (row == 64) ? one : zero;
        }
    }

    attn_issue(sb, 0, Kg, Vtg, 0, t);
    CP_COMMIT();

    float o[2][8][4];
    float ol[2][4];   // ones-column accumulator: l at c0 (row g) / c2 (row g+8), tig==0
#pragma unroll
    for (int mt = 0; mt < 2; mt++) {
#pragma unroll
        for (int nj = 0; nj < 8; nj++)
#pragma unroll
            for (int r = 0; r < 4; r++) o[mt][nj][r] = 0.f;
#pragma unroll
        for (int r = 0; r < 4; r++) ol[mt][r] = 0.f;
    }
    float mr[2][2] = {{-1e30f, -1e30f}, {-1e30f, -1e30f}};

    for (int kt = 0; kt < NIT; kt++) {
        CP_WAIT0();
        __syncthreads();
        if (kt + 1 < NIT) {
            attn_issue(sb, (kt + 1) & 1, Kg, Vtg, kt + 1, t);
            CP_COMMIT();
        }
        uint32_t kb = sb + ((kt & 1) ? AK1 : AK0) * 2;

        // S = Q K^T (log2 domain), 32 rows x 64 keys per warp
        float s[2][8][4];
#pragma unroll
        for (int mt = 0; mt < 2; mt++)
#pragma unroll
            for (int nj = 0; nj < 8; nj++)
#pragma unroll
                for (int r = 0; r < 4; r++) s[mt][nj][r] = 0.f;

#pragma unroll
        for (int ks = 0; ks < 4; ks++)
#pragma unroll
            for (int p = 0; p < 4; p++) {
                uint32_t bf[4];
                ldsm4(bf, b_addr_h(kb, 72, p * 16, ks * 16, lane));
                mma16(s[0][p * 2],     qa[ks][0], bf);
                mma16(s[0][p * 2 + 1], qa[ks][0], bf + 2);
                mma16(s[1][p * 2],     qa[ks][1], bf);
                mma16(s[1][p * 2 + 1], qa[ks][1], bf + 2);
            }

        // Online softmax in log2 domain; exp via f16x2 -> packed fragments pp
        uint32_t pp[2][8][2];
        float corr[2][2];
#pragma unroll
        for (int mt = 0; mt < 2; mt++) {
            float mx0 = mr[mt][0], mx1 = mr[mt][1];
#pragma unroll
            for (int nj = 0; nj < 8; nj++) {
                mx0 = fmaxf(mx0, fmaxf(s[mt][nj][0], s[mt][nj][1]));
                mx1 = fmaxf(mx1, fmaxf(s[mt][nj][2], s[mt][nj][3]));
            }
            mx0 = fmaxf(mx0, __shfl_xor_sync(0xffffffffu, mx0, 1));
            mx0 = fmaxf(mx0, __shfl_xor_sync(0xffffffffu, mx0, 2));
            mx1 = fmaxf(mx1, __shfl_xor_sync(0xffffffffu, mx1, 1));
            mx1 = fmaxf(mx1, __shfl_xor_sync(0xffffffffu, mx1, 2));

            corr[mt][0] = exp2f(mr[mt][0] - mx0);
            corr[mt][1] = exp2f(mr[mt][1] - mx1);
#pragma unroll
            for (int nj = 0; nj < 8; nj++) {
                pp[mt][nj][0] = ex2_h2(f2h2(s[mt][nj][0] - mx0, s[mt][nj][1] - mx0));
                pp[mt][nj][1] = ex2_h2(f2h2(s[mt][nj][2] - mx1, s[mt][nj][3] - mx1));
            }
            mr[mt][0] = mx0; mr[mt][1] = mx1;

#pragma unroll
            for (int nj = 0; nj < 8; nj++) {
                o[mt][nj][0] *= corr[mt][0]; o[mt][nj][1] *= corr[mt][0];
                o[mt][nj][2] *= corr[mt][1]; o[mt][nj][3] *= corr[mt][1];
            }
            ol[mt][0] *= corr[mt][0]; ol[mt][1] *= corr[mt][0];
            ol[mt][2] *= corr[mt][1]; ol[mt][3] *= corr[mt][1];
        }

        // O += P V  and  l += P 1 (ones-column octet at n0=64)
        uint32_t vb = sb + ((kt & 1) ? AV1 : AV0) * 2;
#pragma unroll
        for (int ks = 0; ks < 4; ks++) {
            uint32_t pa0[4] = { pp[0][2*ks][0], pp[0][2*ks][1],
                                pp[0][2*ks+1][0], pp[0][2*ks+1][1] };
            uint32_t pa1[4] = { pp[1][2*ks][0], pp[1][2*ks][1],
                                pp[1][2*ks+1][0], pp[1][2*ks+1][1] };
#pragma unroll
            for (int p = 0; p < 4; p++) {
                uint32_t bf[4];
                ldsm4(bf, b_addr_h(vb, 72, p * 16, ks * 16, lane));
                mma16(o[0][p * 2],     pa0, bf);
                mma16(o[0][p * 2 + 1], pa0, bf + 2);
                mma16(o[1][p * 2],     pa1, bf);
                mma16(o[1][p * 2 + 1], pa1, bf + 2);
            }
            uint32_t bo_[4];
            ldsm4(bo_, b_addr_h(vb, 72, 64, ks * 16, lane));
            mma16(ol[0], pa0, bo_);
            mma16(ol[1], pa1, bo_);
        }
    }

    // Epilogue: l lives in tig==0 lanes (col 64); broadcast within quad.
    const int b_ = bh >> 3, h = bh & 7;
    const int tig = lane & 3;
#pragma unroll
    for (int mt = 0; mt < 2; mt++) {
        float l0 = __shfl_sync(0xffffffffu, ol[mt][0], lane & ~3);
        float l1 = __shfl_sync(0xffffffffu, ol[mt][2], lane & ~3);
        float inv0 = 1.f / l0, inv1 = 1.f / l1;
        int r0 = qt * 128 + mrow + 16 * mt + g;
        __half* p0 = g_A + ((size_t)(b_ * SS + r0)) * HID + h * 64;
        __half* p1 = p0 + (size_t)8 * HID;
#pragma unroll
        for (int nj = 0; nj < 8; nj++) {
            *(uint32_t*)&p0[nj * 8 + 2 * tig] =
                f2h2(o[mt][nj][0] * inv0, o[mt][nj][1] * inv0);
            *(uint32_t*)&p1[nj * 8 + 2 * tig] =
                f2h2(o[mt][nj][2] * inv1, o[mt][nj][3] * inv1);
        }
    }
}

// ===========================================================================
extern "C" void kernel_launch(void* const* d_in, const int* in_sizes, int n_in,
                              void* d_out, int out_size)
{
    const float* X  = (const float*)d_in[0];
    const float* Wq = (const float*)d_in[1];
    const float* bq = (const float*)d_in[2];
    const float* Wk = (const float*)d_in[3];
    const float* bk = (const float*)d_in[4];
    const float* Wv = (const float*)d_in[5];
    const float* bv = (const float*)d_in[6];
    const float* Wo = (const float*)d_in[7];
    const float* bo = (const float*)d_in[8];
    float* out = (float*)d_out;

    cudaFuncSetAttribute(qkv_mma,   cudaFuncAttributeMaxDynamicSharedMemorySize, PROJ_SMEM);
    cudaFuncSetAttribute(oproj_mma, cudaFuncAttributeMaxDynamicSharedMemorySize, PROJ_SMEM);
    cudaFuncSetAttribute(attn_mma,  cudaFuncAttributeMaxDynamicSharedMemorySize, ATTN_SMEM);

    round_x<<<592, 256>>>(X);
    round_wt<<<dim3(24, 24, 4), 256>>>(Wq, Wk, Wv, Wo);
    qkv_mma<<<dim3(HID / 128, MM / 128, 3), 128, PROJ_SMEM>>>(bq, bk, bv);
    attn_mma<<<dim3(SS / 128, NB * NH), 128, ATTN_SMEM>>>();
    oproj_mma<<<dim3(VD / 128, MM / 128), 128, PROJ_SMEM>>>(bo, out);
}